// round 5
// baseline (speedup 1.0000x reference)
#include <cuda_runtime.h>
#include <cuda_bf16.h>
#include <cstdint>

#define NS 1024
#define ND 256
#define NH 8
#define HD 2048

// ---------------- scratch (static device memory; no allocs) ----------------
__device__ __nv_bfloat16 g_Xhi[2097152],  g_Xlo[2097152];
__device__ __nv_bfloat16 g_Wqhi[524288],  g_Wqlo[524288];
__device__ __nv_bfloat16 g_Wkhi[524288],  g_Wklo[524288];
__device__ __nv_bfloat16 g_Wvhi[524288],  g_Wvlo[524288];
__device__ __nv_bfloat16 g_Wphi[524288],  g_Wplo[524288];
__device__ __nv_bfloat16 g_Qhi[16777216], g_Qlo[16777216];
__device__ __nv_bfloat16 g_Khi[16777216], g_Klo[16777216];
__device__ __nv_bfloat16 g_Vhi[16777216], g_Vlo[16777216];
__device__ __nv_bfloat16 g_Vthi[16777216], g_Vtlo[16777216];     // V transposed [bh, e, t]
__device__ __nv_bfloat16 g_Ohi[16777216], g_Olo[16777216];       // [B*S, H*D] concat layout

// ---------------- helpers ----------------
__device__ __forceinline__ uint32_t smem_u32(const void* p) {
    uint32_t a;
    asm("{ .reg .u64 t; cvta.to.shared.u64 t, %1; cvt.u32.u64 %0, t; }" : "=r"(a) : "l"(p));
    return a;
}

__device__ __forceinline__ void split_store2(float a, float b,
                                             __nv_bfloat16* dhi, __nv_bfloat16* dlo) {
    __nv_bfloat16 h0 = __float2bfloat16_rn(a), h1 = __float2bfloat16_rn(b);
    __nv_bfloat16 l0 = __float2bfloat16_rn(a - __bfloat162float(h0));
    __nv_bfloat16 l1 = __float2bfloat16_rn(b - __bfloat162float(h1));
    *(uint32_t*)dhi = (uint32_t)__bfloat16_as_ushort(h0) | ((uint32_t)__bfloat16_as_ushort(h1) << 16);
    *(uint32_t*)dlo = (uint32_t)__bfloat16_as_ushort(l0) | ((uint32_t)__bfloat16_as_ushort(l1) << 16);
}

__device__ __forceinline__ void split2(float a, float b, uint32_t& hi, uint32_t& lo) {
    __nv_bfloat16 h0 = __float2bfloat16_rn(a), h1 = __float2bfloat16_rn(b);
    __nv_bfloat16 l0 = __float2bfloat16_rn(a - __bfloat162float(h0));
    __nv_bfloat16 l1 = __float2bfloat16_rn(b - __bfloat162float(h1));
    hi = (uint32_t)__bfloat16_as_ushort(h0) | ((uint32_t)__bfloat16_as_ushort(h1) << 16);
    lo = (uint32_t)__bfloat16_as_ushort(l0) | ((uint32_t)__bfloat16_as_ushort(l1) << 16);
}

#define CP_ASYNC16(saddr, gptr) \
    asm volatile("cp.async.cg.shared.global [%0], [%1], 16;" :: "r"(saddr), "l"(gptr))
#define CP_COMMIT() asm volatile("cp.async.commit_group;")
#define CP_WAIT1()  asm volatile("cp.async.wait_group 1;")
#define CP_WAIT0()  asm volatile("cp.async.wait_group 0;")
#define LDMX4(r0, r1, r2, r3, addr) \
    asm volatile("ldmatrix.sync.aligned.m8n8.x4.shared.b16 {%0,%1,%2,%3}, [%4];" \
        : "=r"(r0), "=r"(r1), "=r"(r2), "=r"(r3) : "r"(addr))
#define MMA16816(acc, af, b0, b1) \
    asm volatile("mma.sync.aligned.m16n8k16.row.col.f32.bf16.bf16.f32 " \
        "{%0,%1,%2,%3}, {%4,%5,%6,%7}, {%8,%9}, {%0,%1,%2,%3};" \
        : "+f"((acc)[0]), "+f"((acc)[1]), "+f"((acc)[2]), "+f"((acc)[3]) \
        : "r"((af)[0]), "r"((af)[1]), "r"((af)[2]), "r"((af)[3]), "r"(b0), "r"(b1))

// ---------------------------------------------------------------------------
// Warp-MMA GEMM mainloop (HMMA path). C[128,128] = 3-pass split NT GEMM.
// 8 warps 2(M)x4(N), warp tile 64x32, BK=32, double-buffered cp.async.
// ---------------------------------------------------------------------------
__device__ __forceinline__ void mma_gemm(
    const __nv_bfloat16* __restrict__ Ahi, const __nv_bfloat16* __restrict__ Alo,
    const __nv_bfloat16* __restrict__ Bhi, const __nv_bfloat16* __restrict__ Blo,
    int ldA, int ldB, int ksteps, float acc[4][4][4])
{
    __shared__ __nv_bfloat16 sA[2][128][40];
    __shared__ __nv_bfloat16 sB[2][128][40];

    int t = threadIdx.x;
    int lane = t & 31, wid = t >> 5;
    int wm = wid & 1, wn = wid >> 1;

    #pragma unroll
    for (int mf = 0; mf < 4; mf++)
        #pragma unroll
        for (int nf = 0; nf < 4; nf++)
            #pragma unroll
            for (int e = 0; e < 4; e++) acc[mf][nf][e] = 0.f;

    int total = 3 * ksteps;

    auto load_tile = [&](int c, int buf) {
        int pass = c / ksteps, kc = c - pass * ksteps;
        const __nv_bfloat16* Ap = (pass == 1) ? Alo : Ahi;
        const __nv_bfloat16* Bp = (pass == 2) ? Blo : Bhi;
        size_t kbase = (size_t)kc * 32;
        #pragma unroll
        for (int i = 0; i < 2; i++) {
            int idx = t + (i << 8);
            int row = idx >> 2, q = idx & 3;
            CP_ASYNC16(smem_u32(&sA[buf][row][q * 8]), Ap + (size_t)row * ldA + kbase + q * 8);
            CP_ASYNC16(smem_u32(&sB[buf][row][q * 8]), Bp + (size_t)row * ldB + kbase + q * 8);
        }
        CP_COMMIT();
    };

    load_tile(0, 0);

    for (int c = 0; c < total; c++) {
        if (c + 1 < total) { load_tile(c + 1, (c + 1) & 1); CP_WAIT1(); }
        else               { CP_WAIT0(); }
        __syncthreads();

        int buf = c & 1;
        #pragma unroll
        for (int k16 = 0; k16 < 2; k16++) {
            uint32_t af[4][4];
            #pragma unroll
            for (int mf = 0; mf < 4; mf++) {
                int row = wm * 64 + mf * 16 + (lane & 15);
                int ko  = k16 * 16 + (lane >> 4) * 8;
                LDMX4(af[mf][0], af[mf][1], af[mf][2], af[mf][3], smem_u32(&sA[buf][row][ko]));
            }
            uint32_t bfr[4][2];
            #pragma unroll
            for (int p = 0; p < 2; p++) {
                int nrow = wn * 32 + p * 16 + (lane & 7) + ((lane >> 4) << 3);
                int ko   = k16 * 16 + ((lane >> 3) & 1) * 8;
                uint32_t r0, r1, r2, r3;
                LDMX4(r0, r1, r2, r3, smem_u32(&sB[buf][nrow][ko]));
                bfr[2*p][0] = r0; bfr[2*p][1] = r1;
                bfr[2*p+1][0] = r2; bfr[2*p+1][1] = r3;
            }
            #pragma unroll
            for (int mf = 0; mf < 4; mf++)
                #pragma unroll
                for (int nf = 0; nf < 4; nf++)
                    MMA16816(acc[mf][nf], af[mf], bfr[nf][0], bfr[nf][1]);
        }
        __syncthreads();
    }
}

// ---------------------------------------------------------------------------
// Kernel: split fp32 -> bf16 hi/lo
// ---------------------------------------------------------------------------
__global__ __launch_bounds__(256) void split_kernel(
    const float* __restrict__ src, __nv_bfloat16* __restrict__ hi,
    __nv_bfloat16* __restrict__ lo, int n4)
{
    int i = blockIdx.x * 256 + threadIdx.x;
    if (i >= n4) return;
    float4 v = *(const float4*)(src + 4 * (size_t)i);
    uint32_t ph[2], pl[2];
    split2(v.x, v.y, ph[0], pl[0]);
    split2(v.z, v.w, ph[1], pl[1]);
    *(uint2*)((char*)hi + 8 * (size_t)i) = make_uint2(ph[0], ph[1]);
    *(uint2*)((char*)lo + 8 * (size_t)i) = make_uint2(pl[0], pl[1]);
}

// ---------------------------------------------------------------------------
// Kernel: QKV projection.  grid (8, 2, 192): z = qkv*64 + b*8 + h
// ---------------------------------------------------------------------------
__global__ __launch_bounds__(256) void qkv_g(
    const float* __restrict__ bq, const float* __restrict__ bk, const float* __restrict__ bv)
{
    int z = blockIdx.z, qkv = z >> 6, bh = z & 63, b = bh >> 3, h = bh & 7;
    int m0 = blockIdx.x * 128, n0 = blockIdx.y * 128;

    const __nv_bfloat16* Whi = (qkv == 0) ? g_Wqhi : (qkv == 1) ? g_Wkhi : g_Wvhi;
    const __nv_bfloat16* Wlo = (qkv == 0) ? g_Wqlo : (qkv == 1) ? g_Wklo : g_Wvlo;
    const float* bias = ((qkv == 0) ? bq : (qkv == 1) ? bk : bv) + h * ND + n0;

    float acc[4][4][4];
    mma_gemm(g_Xhi + ((size_t)b * NS + m0) * ND, g_Xlo + ((size_t)b * NS + m0) * ND,
             Whi + (size_t)h * ND * ND + (size_t)n0 * ND,
             Wlo + (size_t)h * ND * ND + (size_t)n0 * ND,
             ND, ND, 8, acc);

    __nv_bfloat16* Ohi = (qkv == 0) ? g_Qhi : (qkv == 1) ? g_Khi : g_Vhi;
    __nv_bfloat16* Olo = (qkv == 0) ? g_Qlo : (qkv == 1) ? g_Klo : g_Vlo;

    int lane = threadIdx.x & 31, wid = threadIdx.x >> 5;
    int wm = wid & 1, wn = wid >> 1;
    #pragma unroll
    for (int mf = 0; mf < 4; mf++) {
        int r = m0 + wm * 64 + mf * 16 + (lane >> 2);
        #pragma unroll
        for (int nf = 0; nf < 4; nf++) {
            int cc = wn * 32 + nf * 8 + ((lane & 3) << 1);
            float2 bb = *(const float2*)(bias + cc);
            size_t base0 = ((size_t)bh * NS + r) * ND + n0 + cc;
            size_t base1 = base0 + 8 * ND;
            split_store2(acc[mf][nf][0] + bb.x, acc[mf][nf][1] + bb.y, Ohi + base0, Olo + base0);
            split_store2(acc[mf][nf][2] + bb.x, acc[mf][nf][3] + bb.y, Ohi + base1, Olo + base1);
        }
    }
}

// ---------------------------------------------------------------------------
// Kernel: V transpose [bh,t,e] -> [bh,e,t] (hi+lo). grid (32, 8, 64), block (32,8)
// ---------------------------------------------------------------------------
__global__ void vt_kernel()
{
    __shared__ __nv_bfloat16 th[32][33], tl[32][33];
    int bh = blockIdx.z, t0 = blockIdx.x * 32, e0 = blockIdx.y * 32;
    int tx = threadIdx.x, ty = threadIdx.y;
    #pragma unroll
    for (int j = 0; j < 4; j++) {
        int rr = ty + j * 8;
        size_t idx = ((size_t)bh * NS + t0 + rr) * ND + e0 + tx;
        th[rr][tx] = g_Vhi[idx];
        tl[rr][tx] = g_Vlo[idx];
    }
    __syncthreads();
    #pragma unroll
    for (int j = 0; j < 4; j++) {
        int er = ty + j * 8;
        size_t idx = ((size_t)bh * ND + e0 + er) * NS + t0 + tx;
        g_Vthi[idx] = th[tx][er];
        g_Vtlo[idx] = tl[tx][er];
    }
}

// ---------------------------------------------------------------------------
// Flash attention kernel: scores + softmax + PV fused.  grid (16, 1, 64).
// Block 256 thr = 8 warps (2M x 4N).  Q tile 64 rows; 8 KV tiles of 128.
// S[64x128] in regs; P -> smem bf16 hi/lo; O[64x256] fp32 in regs.
// Dynamic smem layout (bytes):
//   sA  [2][64][40]  bf16   @ 0       (10240)
//   sB  [2][128][40] bf16   @ 10240   (20480)
//   sV  [2][256][40] bf16   @ 30720   (40960)
//   sPh [64][136]    bf16   @ 71680   (17408)
//   sPl [64][136]    bf16   @ 89088   (17408)
//   redA[64][4] f32         @ 106496  (1024)
//   redB[64][4] f32         @ 107520  (1024)   total 108544
// ---------------------------------------------------------------------------
#define FL_SMEM 108544

__global__ __launch_bounds__(256) void flash_g()
{
    extern __shared__ char sm[];
    __nv_bfloat16* sA  = (__nv_bfloat16*)(sm);
    __nv_bfloat16* sB  = (__nv_bfloat16*)(sm + 10240);
    __nv_bfloat16* sV  = (__nv_bfloat16*)(sm + 30720);
    __nv_bfloat16* sPh = (__nv_bfloat16*)(sm + 71680);
    __nv_bfloat16* sPl = (__nv_bfloat16*)(sm + 89088);
    float* redA = (float*)(sm + 106496);
    float* redB = (float*)(sm + 107520);

    int bh = blockIdx.z, b = bh >> 3, hh = bh & 7;
    int m0 = blockIdx.x * 64;
    int t = threadIdx.x, lane = t & 31, wid = t >> 5;
    int wm = wid & 1, wn = wid >> 1;

    const __nv_bfloat16* Qh = g_Qhi + ((size_t)bh * NS + m0) * ND;
    const __nv_bfloat16* Ql = g_Qlo + ((size_t)bh * NS + m0) * ND;
    const __nv_bfloat16* Kh = g_Khi + (size_t)bh * NS * ND;
    const __nv_bfloat16* Kl = g_Klo + (size_t)bh * NS * ND;
    const __nv_bfloat16* Vh = g_Vthi + (size_t)bh * ND * NS;
    const __nv_bfloat16* Vl = g_Vtlo + (size_t)bh * ND * NS;

    float o[2][8][4];
    #pragma unroll
    for (int mf = 0; mf < 2; mf++)
        #pragma unroll
        for (int nf = 0; nf < 8; nf++)
            #pragma unroll
            for (int e = 0; e < 4; e++) o[mf][nf][e] = 0.f;
    float mst[2][2] = {{-1e30f, -1e30f}, {-1e30f, -1e30f}};
    float lst[2][2] = {{0.f, 0.f}, {0.f, 0.f}};

    for (int j = 0; j < 8; j++) {
        int t0 = j * 128;

        // ---- Phase A: S = QK^T (3-pass split, 24 chunks of BK=32) ----
        float s[2][4][4];
        #pragma unroll
        for (int mf = 0; mf < 2; mf++)
            #pragma unroll
            for (int nf = 0; nf < 4; nf++)
                #pragma unroll
                for (int e = 0; e < 4; e++) s[mf][nf][e] = 0.f;

        auto loadS = [&](int c, int buf) {
            int pass = c >> 3, kc = c & 7;
            const __nv_bfloat16* Ap = (pass == 1) ? Ql : Qh;
            const __nv_bfloat16* Bp = (pass == 2) ? Kl : Kh;
            size_t kb = (size_t)kc * 32;
            {   // A: 64 rows, 1 op/thread
                int row = t >> 2, q = t & 3;
                CP_ASYNC16(smem_u32(sA + ((size_t)buf * 64 + row) * 40 + q * 8),
                           Ap + (size_t)row * ND + kb + q * 8);
            }
            #pragma unroll
            for (int i = 0; i < 2; i++) {   // B: 128 rows, 2 ops/thread
                int idx = t + (i << 8);
                int row = idx >> 2, q = idx & 3;
                CP_ASYNC16(smem_u32(sB + ((size_t)buf * 128 + row) * 40 + q * 8),
                           Bp + (size_t)(t0 + row) * ND + kb + q * 8);
            }
            CP_COMMIT();
        };

        loadS(0, 0);
        for (int c = 0; c < 24; c++) {
            if (c + 1 < 24) { loadS(c + 1, (c + 1) & 1); CP_WAIT1(); }
            else            { CP_WAIT0(); }
            __syncthreads();
            int buf = c & 1;
            #pragma unroll
            for (int k16 = 0; k16 < 2; k16++) {
                uint32_t af[2][4];
                #pragma unroll
                for (int mf = 0; mf < 2; mf++) {
                    int row = wm * 32 + mf * 16 + (lane & 15);
                    int ko  = k16 * 16 + (lane >> 4) * 8;
                    LDMX4(af[mf][0], af[mf][1], af[mf][2], af[mf][3],
                          smem_u32(sA + ((size_t)buf * 64 + row) * 40 + ko));
                }
                uint32_t bfr[4][2];
                #pragma unroll
                for (int p = 0; p < 2; p++) {
                    int nrow = wn * 32 + p * 16 + (lane & 7) + ((lane >> 4) << 3);
                    int ko   = k16 * 16 + ((lane >> 3) & 1) * 8;
                    uint32_t r0, r1, r2, r3;
                    LDMX4(r0, r1, r2, r3, smem_u32(sB + ((size_t)buf * 128 + nrow) * 40 + ko));
                    bfr[2*p][0] = r0; bfr[2*p][1] = r1;
                    bfr[2*p+1][0] = r2; bfr[2*p+1][1] = r3;
                }
                #pragma unroll
                for (int mf = 0; mf < 2; mf++)
                    #pragma unroll
                    for (int nf = 0; nf < 4; nf++)
                        MMA16816(s[mf][nf], af[mf], bfr[nf][0], bfr[nf][1]);
            }
            __syncthreads();
        }

        // scale 1/sqrt(D)
        #pragma unroll
        for (int mf = 0; mf < 2; mf++)
            #pragma unroll
            for (int nf = 0; nf < 4; nf++)
                #pragma unroll
                for (int e = 0; e < 4; e++) s[mf][nf][e] *= 0.0625f;

        // ---- Phase B: online softmax ----
        float pm[2][2];
        #pragma unroll
        for (int mf = 0; mf < 2; mf++)
            #pragma unroll
            for (int h = 0; h < 2; h++) {
                float v = -1e30f;
                #pragma unroll
                for (int nf = 0; nf < 4; nf++)
                    v = fmaxf(v, fmaxf(s[mf][nf][h*2], s[mf][nf][h*2+1]));
                v = fmaxf(v, __shfl_xor_sync(0xffffffffu, v, 1));
                v = fmaxf(v, __shfl_xor_sync(0xffffffffu, v, 2));
                pm[mf][h] = v;
            }
        if ((lane & 3) == 0) {
            #pragma unroll
            for (int mf = 0; mf < 2; mf++)
                #pragma unroll
                for (int h = 0; h < 2; h++) {
                    int row = wm * 32 + mf * 16 + (lane >> 2) + h * 8;
                    redA[row * 4 + wn] = pm[mf][h];
                }
        }
        __syncthreads();

        float fsc[2][2], mnew[2][2];
        #pragma unroll
        for (int mf = 0; mf < 2; mf++)
            #pragma unroll
            for (int h = 0; h < 2; h++) {
                int row = wm * 32 + mf * 16 + (lane >> 2) + h * 8;
                float tm = fmaxf(fmaxf(redA[row*4], redA[row*4+1]),
                                 fmaxf(redA[row*4+2], redA[row*4+3]));
                float mn = fmaxf(mst[mf][h], tm);
                fsc[mf][h] = __expf(mst[mf][h] - mn);
                mnew[mf][h] = mn;
                mst[mf][h] = mn;
            }

        // p = exp(s - m), write split P to smem, accumulate row sums
        float psum[2][2];
        #pragma unroll
        for (int mf = 0; mf < 2; mf++)
            #pragma unroll
            for (int h = 0; h < 2; h++) {
                int row = wm * 32 + mf * 16 + (lane >> 2) + h * 8;
                float sum = 0.f;
                #pragma unroll
                for (int nf = 0; nf < 4; nf++) {
                    float p0 = __expf(s[mf][nf][h*2]   - mnew[mf][h]);
                    float p1 = __expf(s[mf][nf][h*2+1] - mnew[mf][h]);
                    sum += p0 + p1;
                    int cc = wn * 32 + nf * 8 + ((lane & 3) << 1);
                    uint32_t hi, lo;
                    split2(p0, p1, hi, lo);
                    *(uint32_t*)(sPh + (size_t)row * 136 + cc) = hi;
                    *(uint32_t*)(sPl + (size_t)row * 136 + cc) = lo;
                }
                sum += __shfl_xor_sync(0xffffffffu, sum, 1);
                sum += __shfl_xor_sync(0xffffffffu, sum, 2);
                psum[mf][h] = sum;
            }
        if ((lane & 3) == 0) {
            #pragma unroll
            for (int mf = 0; mf < 2; mf++)
                #pragma unroll
                for (int h = 0; h < 2; h++) {
                    int row = wm * 32 + mf * 16 + (lane >> 2) + h * 8;
                    redB[row * 4 + wn] = psum[mf][h];
                }
        }
        __syncthreads();
        #pragma unroll
        for (int mf = 0; mf < 2; mf++)
            #pragma unroll
            for (int h = 0; h < 2; h++) {
                int row = wm * 32 + mf * 16 + (lane >> 2) + h * 8;
                float ts = redB[row*4] + redB[row*4+1] + redB[row*4+2] + redB[row*4+3];
                lst[mf][h] = lst[mf][h] * fsc[mf][h] + ts;
            }

        // rescale O
        #pragma unroll
        for (int mf = 0; mf < 2; mf++)
            #pragma unroll
            for (int nf = 0; nf < 8; nf++) {
                o[mf][nf][0] *= fsc[mf][0]; o[mf][nf][1] *= fsc[mf][0];
                o[mf][nf][2] *= fsc[mf][1]; o[mf][nf][3] *= fsc[mf][1];
            }

        // ---- Phase C: O += P @ V^T tile (3 passes x 4 chunks of 32) ----
        auto loadV = [&](int c, int buf) {
            int pass = c >> 2, ck = c & 3;
            const __nv_bfloat16* Bp = (pass == 2) ? Vl : Vh;
            size_t kb = (size_t)t0 + ck * 32;
            #pragma unroll
            for (int i = 0; i < 4; i++) {    // 256 rows, 4 ops/thread
                int idx = t + (i << 8);
                int row = idx >> 2, q = idx & 3;
                CP_ASYNC16(smem_u32(sV + ((size_t)buf * 256 + row) * 40 + q * 8),
                           Bp + (size_t)row * NS + kb + q * 8);
            }
            CP_COMMIT();
        };

        loadV(0, 0);
        for (int c = 0; c < 12; c++) {
            if (c + 1 < 12) { loadV(c + 1, (c + 1) & 1); CP_WAIT1(); }
            else            { CP_WAIT0(); }
            __syncthreads();
            int pass = c >> 2, ck = c & 3, buf = c & 1;
            const __nv_bfloat16* sPx = (pass == 1) ? sPl : sPh;
            #pragma unroll
            for (int k16 = 0; k16 < 2; k16++) {
                uint32_t af[2][4];
                #pragma unroll
                for (int mf = 0; mf < 2; mf++) {
                    int row = wm * 32 + mf * 16 + (lane & 15);
                    int ko  = ck * 32 + k16 * 16 + (lane >> 4) * 8;
                    LDMX4(af[mf][0], af[mf][1], af[mf][2], af[mf][3],
                          smem_u32(sPx + (size_t)row * 136 + ko));
                }
                uint32_t bfr[8][2];
                #pragma unroll
                for (int p = 0; p < 4; p++) {
                    int nrow = wn * 64 + p * 16 + (lane & 7) + ((lane >> 4) << 3);
                    int ko   = k16 * 16 + ((lane >> 3) & 1) * 8;
                    uint32_t r0, r1, r2, r3;
                    LDMX4(r0, r1, r2, r3, smem_u32(sV + ((size_t)buf * 256 + nrow) * 40 + ko));
                    bfr[2*p][0] = r0; bfr[2*p][1] = r1;
                    bfr[2*p+1][0] = r2; bfr[2*p+1][1] = r3;
                }
                #pragma unroll
                for (int mf = 0; mf < 2; mf++)
                    #pragma unroll
                    for (int nf = 0; nf < 8; nf++)
                        MMA16816(o[mf][nf], af[mf], bfr[nf][0], bfr[nf][1]);
            }
            __syncthreads();
        }
    }

    // ---- Epilogue: normalize by 1/l, split-store to concat layout ----
    float inv[2][2];
    #pragma unroll
    for (int mf = 0; mf < 2; mf++)
        #pragma unroll
        for (int h = 0; h < 2; h++) inv[mf][h] = 1.0f / lst[mf][h];

    #pragma unroll
    for (int mf = 0; mf < 2; mf++) {
        #pragma unroll
        for (int h = 0; h < 2; h++) {
            int r = m0 + wm * 32 + mf * 16 + (lane >> 2) + h * 8;
            #pragma unroll
            for (int nf = 0; nf < 8; nf++) {
                int e = wn * 64 + nf * 8 + ((lane & 3) << 1);
                size_t base = ((size_t)(b * NS + r)) * HD + hh * ND + e;
                split_store2(o[mf][nf][h*2] * inv[mf][h], o[mf][nf][h*2+1] * inv[mf][h],
                             g_Ohi + base, g_Olo + base);
            }
        }
    }
}

// ---------------------------------------------------------------------------
// Kernel: out = concat(O) @ Wp^T.  grid (64, 2, 1)
// ---------------------------------------------------------------------------
__global__ __launch_bounds__(256) void proj_g(float* __restrict__ out)
{
    int m0 = blockIdx.x * 128, n0 = blockIdx.y * 128;
    float acc[4][4][4];
    mma_gemm(g_Ohi + (size_t)m0 * HD, g_Olo + (size_t)m0 * HD,
             g_Wphi + (size_t)n0 * HD, g_Wplo + (size_t)n0 * HD,
             HD, HD, 64, acc);

    int lane = threadIdx.x & 31, wid = threadIdx.x >> 5;
    int wm = wid & 1, wn = wid >> 1;
    #pragma unroll
    for (int mf = 0; mf < 4; mf++) {
        int r = m0 + wm * 64 + mf * 16 + (lane >> 2);
        #pragma unroll
        for (int nf = 0; nf < 4; nf++) {
            int cc = n0 + wn * 32 + nf * 8 + ((lane & 3) << 1);
            float* d0 = out + (size_t)r * ND + cc;
            *(float2*)d0 = make_float2(acc[mf][nf][0], acc[mf][nf][1]);
            *(float2*)(d0 + 8 * ND) = make_float2(acc[mf][nf][2], acc[mf][nf][3]);
        }
    }
}

// ---------------------------------------------------------------------------
extern "C" void kernel_launch(void* const* d_in, const int* in_sizes, int n_in,
                              void* d_out, int out_size)
{
    const float* x  = (const float*)d_in[0];
    const float* Wq = (const float*)d_in[1];
    const float* Wk = (const float*)d_in[2];
    const float* Wv = (const float*)d_in[3];
    const float* bq = (const float*)d_in[4];
    const float* bk = (const float*)d_in[5];
    const float* bv = (const float*)d_in[6];
    const float* Wp = (const float*)d_in[7];
    float* out = (float*)d_out;

    cudaFuncSetAttribute(flash_g, cudaFuncAttributeMaxDynamicSharedMemorySize, FL_SMEM);

    __nv_bfloat16 *Xhi, *Xlo, *Wqhi, *Wqlo, *Wkhi, *Wklo, *Wvhi, *Wvlo, *Wphi, *Wplo;
    cudaGetSymbolAddress((void**)&Xhi,  g_Xhi);  cudaGetSymbolAddress((void**)&Xlo,  g_Xlo);
    cudaGetSymbolAddress((void**)&Wqhi, g_Wqhi); cudaGetSymbolAddress((void**)&Wqlo, g_Wqlo);
    cudaGetSymbolAddress((void**)&Wkhi, g_Wkhi); cudaGetSymbolAddress((void**)&Wklo, g_Wklo);
    cudaGetSymbolAddress((void**)&Wvhi, g_Wvhi); cudaGetSymbolAddress((void**)&Wvlo, g_Wvlo);
    cudaGetSymbolAddress((void**)&Wphi, g_Wphi); cudaGetSymbolAddress((void**)&Wplo, g_Wplo);

    split_kernel<<<2048, 256>>>(x,  Xhi,  Xlo,  524288);
    split_kernel<<<512,  256>>>(Wq, Wqhi, Wqlo, 131072);
    split_kernel<<<512,  256>>>(Wk, Wkhi, Wklo, 131072);
    split_kernel<<<512,  256>>>(Wv, Wvhi, Wvlo, 131072);
    split_kernel<<<512,  256>>>(Wp, Wphi, Wplo, 131072);

    dim3 gq(8, 2, 192);
    qkv_g<<<gq, 256>>>(bq, bk, bv);

    dim3 gt(32, 8, 64);
    vt_kernel<<<gt, dim3(32, 8)>>>();

    dim3 gf(16, 1, 64);
    flash_g<<<gf, 256, FL_SMEM>>>();

    dim3 go(64, 2, 1);
    proj_g<<<go, 256>>>(out);
}

// round 7
// speedup vs baseline: 1.4810x; 1.4810x over previous
#include <cuda_runtime.h>
#include <cuda_bf16.h>
#include <cstdint>

#define NS 1024
#define ND 256
#define NH 8
#define HD 2048

// ---------------- scratch (static device memory; no allocs) ----------------
__device__ float g_P[67108864];                                   // 256 MB fp32 scores
__device__ __nv_bfloat16 g_Xhi[2097152],  g_Xlo[2097152];
__device__ __nv_bfloat16 g_Wqhi[524288],  g_Wqlo[524288];
__device__ __nv_bfloat16 g_Wkhi[524288],  g_Wklo[524288];
__device__ __nv_bfloat16 g_Wvhi[524288],  g_Wvlo[524288];
__device__ __nv_bfloat16 g_Wphi[524288],  g_Wplo[524288];
__device__ __nv_bfloat16 g_Qhi[16777216], g_Qlo[16777216];
__device__ __nv_bfloat16 g_Khi[16777216], g_Klo[16777216];
__device__ __nv_bfloat16 g_Vhi[16777216], g_Vlo[16777216];
__device__ __nv_bfloat16 g_Vthi[16777216], g_Vtlo[16777216];     // V transposed [bh, e, t]
__device__ __nv_bfloat16 g_Phi[67108864], g_Plo[67108864];       // softmax probs split
__device__ __nv_bfloat16 g_Ohi[16777216], g_Olo[16777216];       // [B*S, H*D] concat layout

// ---------------- helpers ----------------
__device__ __forceinline__ uint32_t smem_u32(const void* p) {
    uint32_t a;
    asm("{ .reg .u64 t; cvta.to.shared.u64 t, %1; cvt.u32.u64 %0, t; }" : "=r"(a) : "l"(p));
    return a;
}

__device__ __forceinline__ void split_store2(float a, float b,
                                             __nv_bfloat16* dhi, __nv_bfloat16* dlo) {
    __nv_bfloat16 h0 = __float2bfloat16_rn(a), h1 = __float2bfloat16_rn(b);
    __nv_bfloat16 l0 = __float2bfloat16_rn(a - __bfloat162float(h0));
    __nv_bfloat16 l1 = __float2bfloat16_rn(b - __bfloat162float(h1));
    *(uint32_t*)dhi = (uint32_t)__bfloat16_as_ushort(h0) | ((uint32_t)__bfloat16_as_ushort(h1) << 16);
    *(uint32_t*)dlo = (uint32_t)__bfloat16_as_ushort(l0) | ((uint32_t)__bfloat16_as_ushort(l1) << 16);
}

__device__ __forceinline__ void split2(float a, float b, uint32_t& hi, uint32_t& lo) {
    __nv_bfloat16 h0 = __float2bfloat16_rn(a), h1 = __float2bfloat16_rn(b);
    __nv_bfloat16 l0 = __float2bfloat16_rn(a - __bfloat162float(h0));
    __nv_bfloat16 l1 = __float2bfloat16_rn(b - __bfloat162float(h1));
    hi = (uint32_t)__bfloat16_as_ushort(h0) | ((uint32_t)__bfloat16_as_ushort(h1) << 16);
    lo = (uint32_t)__bfloat16_as_ushort(l0) | ((uint32_t)__bfloat16_as_ushort(l1) << 16);
}

#define CP_ASYNC16(saddr, gptr) \
    asm volatile("cp.async.cg.shared.global [%0], [%1], 16;" :: "r"(saddr), "l"(gptr))
#define CP_COMMIT() asm volatile("cp.async.commit_group;")
#define CP_WAIT1()  asm volatile("cp.async.wait_group 1;")
#define CP_WAIT0()  asm volatile("cp.async.wait_group 0;")
#define LDMX4(r0, r1, r2, r3, addr) \
    asm volatile("ldmatrix.sync.aligned.m8n8.x4.shared.b16 {%0,%1,%2,%3}, [%4];" \
        : "=r"(r0), "=r"(r1), "=r"(r2), "=r"(r3) : "r"(addr))
#define MMA16816(acc, af, b0, b1) \
    asm volatile("mma.sync.aligned.m16n8k16.row.col.f32.bf16.bf16.f32 " \
        "{%0,%1,%2,%3}, {%4,%5,%6,%7}, {%8,%9}, {%0,%1,%2,%3};" \
        : "+f"((acc)[0]), "+f"((acc)[1]), "+f"((acc)[2]), "+f"((acc)[3]) \
        : "r"((af)[0]), "r"((af)[1]), "r"((af)[2]), "r"((af)[3]), "r"(b0), "r"(b1))

// ---------------------------------------------------------------------------
// 3-product single-sweep GEMM mainloop.  C[128,128] NT, fp32-split bf16.
// Per K-chunk (BK=32) loads Ahi/Alo/Bhi/Blo tiles, issues
// ahi*bhi + alo*bhi + ahi*blo.  8 warps 2(M)x4(N), warp tile 64x32,
// double-buffered cp.async.  Dynamic smem 81920 B:
//   sAh[2][128][40] @0, sAl @20480, sBh @40960, sBl @61440  (bf16)
// ---------------------------------------------------------------------------
#define G3_SMEM 81920

__device__ __forceinline__ void mma_gemm3(
    const __nv_bfloat16* __restrict__ Ahi, const __nv_bfloat16* __restrict__ Alo,
    const __nv_bfloat16* __restrict__ Bhi, const __nv_bfloat16* __restrict__ Blo,
    int ldA, int ldB, int ksteps, float acc[4][4][4], char* sm)
{
    __nv_bfloat16* sAh = (__nv_bfloat16*)(sm);
    __nv_bfloat16* sAl = (__nv_bfloat16*)(sm + 20480);
    __nv_bfloat16* sBh = (__nv_bfloat16*)(sm + 40960);
    __nv_bfloat16* sBl = (__nv_bfloat16*)(sm + 61440);

    int t = threadIdx.x;
    int lane = t & 31, wid = t >> 5;
    int wm = wid & 1, wn = wid >> 1;

    #pragma unroll
    for (int mf = 0; mf < 4; mf++)
        #pragma unroll
        for (int nf = 0; nf < 4; nf++)
            #pragma unroll
            for (int e = 0; e < 4; e++) acc[mf][nf][e] = 0.f;

    auto load_tile = [&](int kc, int buf) {
        size_t kbase = (size_t)kc * 32;
        #pragma unroll
        for (int i = 0; i < 2; i++) {
            int idx = t + (i << 8);
            int row = idx >> 2, q = idx & 3;
            size_t aoff = (size_t)row * ldA + kbase + q * 8;
            size_t boff = (size_t)row * ldB + kbase + q * 8;
            uint32_t so = (uint32_t)((buf * 128 + row) * 40 + q * 8);
            CP_ASYNC16(smem_u32(sAh + so), Ahi + aoff);
            CP_ASYNC16(smem_u32(sAl + so), Alo + aoff);
            CP_ASYNC16(smem_u32(sBh + so), Bhi + boff);
            CP_ASYNC16(smem_u32(sBl + so), Blo + boff);
        }
        CP_COMMIT();
    };

    load_tile(0, 0);

    for (int c = 0; c < ksteps; c++) {
        if (c + 1 < ksteps) { load_tile(c + 1, (c + 1) & 1); CP_WAIT1(); }
        else                { CP_WAIT0(); }
        __syncthreads();

        int buf = c & 1;
        #pragma unroll
        for (int k16 = 0; k16 < 2; k16++) {
            uint32_t afh[4][4], afl[4][4];
            #pragma unroll
            for (int mf = 0; mf < 4; mf++) {
                int row = wm * 64 + mf * 16 + (lane & 15);
                int ko  = k16 * 16 + (lane >> 4) * 8;
                uint32_t so = (uint32_t)((buf * 128 + row) * 40 + ko);
                LDMX4(afh[mf][0], afh[mf][1], afh[mf][2], afh[mf][3], smem_u32(sAh + so));
                LDMX4(afl[mf][0], afl[mf][1], afl[mf][2], afl[mf][3], smem_u32(sAl + so));
            }
            uint32_t bfh[4][2], bfl[4][2];
            #pragma unroll
            for (int p = 0; p < 2; p++) {
                int nrow = wn * 32 + p * 16 + (lane & 7) + ((lane >> 4) << 3);
                int ko   = k16 * 16 + ((lane >> 3) & 1) * 8;
                uint32_t so = (uint32_t)((buf * 128 + nrow) * 40 + ko);
                uint32_t r0, r1, r2, r3;
                LDMX4(r0, r1, r2, r3, smem_u32(sBh + so));
                bfh[2*p][0] = r0; bfh[2*p][1] = r1;
                bfh[2*p+1][0] = r2; bfh[2*p+1][1] = r3;
                LDMX4(r0, r1, r2, r3, smem_u32(sBl + so));
                bfl[2*p][0] = r0; bfl[2*p][1] = r1;
                bfl[2*p+1][0] = r2; bfl[2*p+1][1] = r3;
            }
            #pragma unroll
            for (int mf = 0; mf < 4; mf++)
                #pragma unroll
                for (int nf = 0; nf < 4; nf++) {
                    MMA16816(acc[mf][nf], afh[mf], bfh[nf][0], bfh[nf][1]);
                    MMA16816(acc[mf][nf], afl[mf], bfh[nf][0], bfh[nf][1]);
                    MMA16816(acc[mf][nf], afh[mf], bfl[nf][0], bfl[nf][1]);
                }
        }
        __syncthreads();
    }
}

// ---------------------------------------------------------------------------
// Kernel: split fp32 -> bf16 hi/lo
// ---------------------------------------------------------------------------
__global__ __launch_bounds__(256) void split_kernel(
    const float* __restrict__ src, __nv_bfloat16* __restrict__ hi,
    __nv_bfloat16* __restrict__ lo, int n4)
{
    int i = blockIdx.x * 256 + threadIdx.x;
    if (i >= n4) return;
    float4 v = *(const float4*)(src + 4 * (size_t)i);
    uint32_t ph[2], pl[2];
    split2(v.x, v.y, ph[0], pl[0]);
    split2(v.z, v.w, ph[1], pl[1]);
    *(uint2*)((char*)hi + 8 * (size_t)i) = make_uint2(ph[0], ph[1]);
    *(uint2*)((char*)lo + 8 * (size_t)i) = make_uint2(pl[0], pl[1]);
}

// ---------------------------------------------------------------------------
// Kernel: QKV projection.  grid (8, 2, 192): z = qkv*64 + b*8 + h
// Q output is pre-scaled by 2^-4 (exact) so scores epilogue has no multiply.
// ---------------------------------------------------------------------------
__global__ __launch_bounds__(256) void qkv_g(
    const float* __restrict__ bq, const float* __restrict__ bk, const float* __restrict__ bv)
{
    extern __shared__ char sm[];
    int z = blockIdx.z, qkv = z >> 6, bh = z & 63, b = bh >> 3, h = bh & 7;
    int m0 = blockIdx.x * 128, n0 = blockIdx.y * 128;

    const __nv_bfloat16* Whi = (qkv == 0) ? g_Wqhi : (qkv == 1) ? g_Wkhi : g_Wvhi;
    const __nv_bfloat16* Wlo = (qkv == 0) ? g_Wqlo : (qkv == 1) ? g_Wklo : g_Wvlo;
    const float* bias = ((qkv == 0) ? bq : (qkv == 1) ? bk : bv) + h * ND + n0;

    float acc[4][4][4];
    mma_gemm3(g_Xhi + ((size_t)b * NS + m0) * ND, g_Xlo + ((size_t)b * NS + m0) * ND,
              Whi + (size_t)h * ND * ND + (size_t)n0 * ND,
              Wlo + (size_t)h * ND * ND + (size_t)n0 * ND,
              ND, ND, 8, acc, sm);

    __nv_bfloat16* Ohi = (qkv == 0) ? g_Qhi : (qkv == 1) ? g_Khi : g_Vhi;
    __nv_bfloat16* Olo = (qkv == 0) ? g_Qlo : (qkv == 1) ? g_Klo : g_Vlo;
    float scale = (qkv == 0) ? 0.0625f : 1.0f;   // exact power of two

    int lane = threadIdx.x & 31, wid = threadIdx.x >> 5;
    int wm = wid & 1, wn = wid >> 1;
    #pragma unroll
    for (int mf = 0; mf < 4; mf++) {
        int r = m0 + wm * 64 + mf * 16 + (lane >> 2);
        #pragma unroll
        for (int nf = 0; nf < 4; nf++) {
            int cc = wn * 32 + nf * 8 + ((lane & 3) << 1);
            float2 bb = *(const float2*)(bias + cc);
            size_t base0 = ((size_t)bh * NS + r) * ND + n0 + cc;
            size_t base1 = base0 + 8 * ND;
            split_store2((acc[mf][nf][0] + bb.x) * scale, (acc[mf][nf][1] + bb.y) * scale,
                         Ohi + base0, Olo + base0);
            split_store2((acc[mf][nf][2] + bb.x) * scale, (acc[mf][nf][3] + bb.y) * scale,
                         Ohi + base1, Olo + base1);
        }
    }
}

// ---------------------------------------------------------------------------
// Kernel: V transpose [bh,t,e] -> [bh,e,t] (hi+lo). grid (32, 8, 64), block (32,8)
// ---------------------------------------------------------------------------
__global__ void vt_kernel()
{
    __shared__ __nv_bfloat16 th[32][33], tl[32][33];
    int bh = blockIdx.z, t0 = blockIdx.x * 32, e0 = blockIdx.y * 32;
    int tx = threadIdx.x, ty = threadIdx.y;
    #pragma unroll
    for (int j = 0; j < 4; j++) {
        int rr = ty + j * 8;
        size_t idx = ((size_t)bh * NS + t0 + rr) * ND + e0 + tx;
        th[rr][tx] = g_Vhi[idx];
        tl[rr][tx] = g_Vlo[idx];
    }
    __syncthreads();
    #pragma unroll
    for (int j = 0; j < 4; j++) {
        int er = ty + j * 8;
        size_t idx = ((size_t)bh * ND + e0 + er) * NS + t0 + tx;
        g_Vthi[idx] = th[tx][er];
        g_Vtlo[idx] = tl[tx][er];
    }
}

// ---------------------------------------------------------------------------
// Kernel: scores = (Q/16) K^T.  grid (8, 8, 64)
// ---------------------------------------------------------------------------
__global__ __launch_bounds__(256) void scores_g()
{
    extern __shared__ char sm[];
    int bh = blockIdx.z, m0 = blockIdx.x * 128, n0 = blockIdx.y * 128;
    float acc[4][4][4];
    mma_gemm3(g_Qhi + ((size_t)bh * NS + m0) * ND, g_Qlo + ((size_t)bh * NS + m0) * ND,
              g_Khi + ((size_t)bh * NS + n0) * ND, g_Klo + ((size_t)bh * NS + n0) * ND,
              ND, ND, 8, acc, sm);

    int lane = threadIdx.x & 31, wid = threadIdx.x >> 5;
    int wm = wid & 1, wn = wid >> 1;
    #pragma unroll
    for (int mf = 0; mf < 4; mf++) {
        int r = m0 + wm * 64 + mf * 16 + (lane >> 2);
        #pragma unroll
        for (int nf = 0; nf < 4; nf++) {
            int cc = n0 + wn * 32 + nf * 8 + ((lane & 3) << 1);
            float* d0 = g_P + ((size_t)bh * NS + r) * NS + cc;
            *(float2*)d0 = make_float2(acc[mf][nf][0], acc[mf][nf][1]);
            *(float2*)(d0 + 8 * NS) = make_float2(acc[mf][nf][2], acc[mf][nf][3]);
        }
    }
}

// ---------------------------------------------------------------------------
// Kernel: softmax over keys + bf16 hi/lo split.  grid 65536, block 256
// ---------------------------------------------------------------------------
__global__ __launch_bounds__(256) void softmax_kernel()
{
    size_t rowoff = (size_t)blockIdx.x * NS;
    const float* p = g_P + rowoff;
    int t = threadIdx.x;
    float4 v = *(const float4*)(p + (t << 2));
    __shared__ float smx[8], ssm[8];

    float m = fmaxf(fmaxf(v.x, v.y), fmaxf(v.z, v.w));
    #pragma unroll
    for (int o = 16; o > 0; o >>= 1) m = fmaxf(m, __shfl_xor_sync(0xffffffffu, m, o));
    if ((t & 31) == 0) smx[t >> 5] = m;
    __syncthreads();
    if (t < 32) {
        float mm = (t < 8) ? smx[t] : -3.0e38f;
        #pragma unroll
        for (int o = 4; o > 0; o >>= 1) mm = fmaxf(mm, __shfl_xor_sync(0xffffffffu, mm, o));
        if (t == 0) smx[0] = mm;
    }
    __syncthreads();
    m = smx[0];
    v.x = __expf(v.x - m); v.y = __expf(v.y - m);
    v.z = __expf(v.z - m); v.w = __expf(v.w - m);
    float s = v.x + v.y + v.z + v.w;
    #pragma unroll
    for (int o = 16; o > 0; o >>= 1) s += __shfl_xor_sync(0xffffffffu, s, o);
    if ((t & 31) == 0) ssm[t >> 5] = s;
    __syncthreads();
    if (t < 32) {
        float sv = (t < 8) ? ssm[t] : 0.f;
        #pragma unroll
        for (int o = 4; o > 0; o >>= 1) sv += __shfl_xor_sync(0xffffffffu, sv, o);
        if (t == 0) ssm[0] = sv;
    }
    __syncthreads();
    float inv = 1.0f / ssm[0];
    float a[4] = {v.x * inv, v.y * inv, v.z * inv, v.w * inv};

    uint32_t ph[2], pl[2];
    split2(a[0], a[1], ph[0], pl[0]);
    split2(a[2], a[3], ph[1], pl[1]);
    *(uint2*)((char*)g_Phi + 2 * (rowoff + (t << 2))) = make_uint2(ph[0], ph[1]);
    *(uint2*)((char*)g_Plo + 2 * (rowoff + (t << 2))) = make_uint2(pl[0], pl[1]);
}

// ---------------------------------------------------------------------------
// Kernel: O = P @ V (B = V^T).  grid (8, 2, 64) -> concat layout
// ---------------------------------------------------------------------------
__global__ __launch_bounds__(256) void pv_g()
{
    extern __shared__ char sm[];
    int bh = blockIdx.z, b = bh >> 3, h = bh & 7;
    int m0 = blockIdx.x * 128, n0 = blockIdx.y * 128;
    float acc[4][4][4];
    mma_gemm3(g_Phi + ((size_t)bh * NS + m0) * NS, g_Plo + ((size_t)bh * NS + m0) * NS,
              g_Vthi + (size_t)bh * ND * NS + (size_t)n0 * NS,
              g_Vtlo + (size_t)bh * ND * NS + (size_t)n0 * NS,
              NS, NS, 32, acc, sm);

    int lane = threadIdx.x & 31, wid = threadIdx.x >> 5;
    int wm = wid & 1, wn = wid >> 1;
    #pragma unroll
    for (int mf = 0; mf < 4; mf++) {
        int r = m0 + wm * 64 + mf * 16 + (lane >> 2);
        #pragma unroll
        for (int nf = 0; nf < 4; nf++) {
            int cc = n0 + wn * 32 + nf * 8 + ((lane & 3) << 1);
            size_t base0 = ((size_t)(b * NS + r)) * HD + h * ND + cc;
            size_t base1 = base0 + 8 * HD;
            split_store2(acc[mf][nf][0], acc[mf][nf][1], g_Ohi + base0, g_Olo + base0);
            split_store2(acc[mf][nf][2], acc[mf][nf][3], g_Ohi + base1, g_Olo + base1);
        }
    }
}

// ---------------------------------------------------------------------------
// Kernel: out = concat(O) @ Wp^T.  grid (64, 2, 1)
// ---------------------------------------------------------------------------
__global__ __launch_bounds__(256) void proj_g(float* __restrict__ out)
{
    extern __shared__ char sm[];
    int m0 = blockIdx.x * 128, n0 = blockIdx.y * 128;
    float acc[4][4][4];
    mma_gemm3(g_Ohi + (size_t)m0 * HD, g_Olo + (size_t)m0 * HD,
              g_Wphi + (size_t)n0 * HD, g_Wplo + (size_t)n0 * HD,
              HD, HD, 64, acc, sm);

    int lane = threadIdx.x & 31, wid = threadIdx.x >> 5;
    int wm = wid & 1, wn = wid >> 1;
    #pragma unroll
    for (int mf = 0; mf < 4; mf++) {
        int r = m0 + wm * 64 + mf * 16 + (lane >> 2);
        #pragma unroll
        for (int nf = 0; nf < 4; nf++) {
            int cc = n0 + wn * 32 + nf * 8 + ((lane & 3) << 1);
            float* d0 = out + (size_t)r * ND + cc;
            *(float2*)d0 = make_float2(acc[mf][nf][0], acc[mf][nf][1]);
            *(float2*)(d0 + 8 * ND) = make_float2(acc[mf][nf][2], acc[mf][nf][3]);
        }
    }
}

// ---------------------------------------------------------------------------
extern "C" void kernel_launch(void* const* d_in, const int* in_sizes, int n_in,
                              void* d_out, int out_size)
{
    const float* x  = (const float*)d_in[0];
    const float* Wq = (const float*)d_in[1];
    const float* Wk = (const float*)d_in[2];
    const float* Wv = (const float*)d_in[3];
    const float* bq = (const float*)d_in[4];
    const float* bk = (const float*)d_in[5];
    const float* bv = (const float*)d_in[6];
    const float* Wp = (const float*)d_in[7];
    float* out = (float*)d_out;

    cudaFuncSetAttribute(qkv_g,    cudaFuncAttributeMaxDynamicSharedMemorySize, G3_SMEM);
    cudaFuncSetAttribute(scores_g, cudaFuncAttributeMaxDynamicSharedMemorySize, G3_SMEM);
    cudaFuncSetAttribute(pv_g,     cudaFuncAttributeMaxDynamicSharedMemorySize, G3_SMEM);
    cudaFuncSetAttribute(proj_g,   cudaFuncAttributeMaxDynamicSharedMemorySize, G3_SMEM);

    __nv_bfloat16 *Xhi, *Xlo, *Wqhi, *Wqlo, *Wkhi, *Wklo, *Wvhi, *Wvlo, *Wphi, *Wplo;
    cudaGetSymbolAddress((void**)&Xhi,  g_Xhi);  cudaGetSymbolAddress((void**)&Xlo,  g_Xlo);
    cudaGetSymbolAddress((void**)&Wqhi, g_Wqhi); cudaGetSymbolAddress((void**)&Wqlo, g_Wqlo);
    cudaGetSymbolAddress((void**)&Wkhi, g_Wkhi); cudaGetSymbolAddress((void**)&Wklo, g_Wklo);
    cudaGetSymbolAddress((void**)&Wvhi, g_Wvhi); cudaGetSymbolAddress((void**)&Wvlo, g_Wvlo);
    cudaGetSymbolAddress((void**)&Wphi, g_Wphi); cudaGetSymbolAddress((void**)&Wplo, g_Wplo);

    split_kernel<<<2048, 256>>>(x,  Xhi,  Xlo,  524288);
    split_kernel<<<512,  256>>>(Wq, Wqhi, Wqlo, 131072);
    split_kernel<<<512,  256>>>(Wk, Wkhi, Wklo, 131072);
    split_kernel<<<512,  256>>>(Wv, Wvhi, Wvlo, 131072);
    split_kernel<<<512,  256>>>(Wp, Wphi, Wplo, 131072);

    dim3 gq(8, 2, 192);
    qkv_g<<<gq, 256, G3_SMEM>>>(bq, bk, bv);

    dim3 gt(32, 8, 64);
    vt_kernel<<<gt, dim3(32, 8)>>>();

    dim3 gs(8, 8, 64);
    scores_g<<<gs, 256, G3_SMEM>>>();

    softmax_kernel<<<65536, 256>>>();

    dim3 gp(8, 2, 64);
    pv_g<<<gp, 256, G3_SMEM>>>();

    dim3 go(64, 2, 1);
    proj_g<<<go, 256, G3_SMEM>>>(out);
}

// round 8
// speedup vs baseline: 1.4858x; 1.0032x over previous
#include <cuda_runtime.h>
#include <cuda_bf16.h>
#include <cstdint>

#define NS 1024
#define ND 256
#define NH 8
#define HD 2048

// ---------------- scratch (static device memory; no allocs) ----------------
__device__ float g_P[67108864];                                   // 256 MB fp32 scores
__device__ __nv_bfloat16 g_Xhi[2097152],  g_Xlo[2097152];
__device__ __nv_bfloat16 g_Wqhi[524288],  g_Wqlo[524288];
__device__ __nv_bfloat16 g_Wkhi[524288],  g_Wklo[524288];
__device__ __nv_bfloat16 g_Wvhi[524288],  g_Wvlo[524288];
__device__ __nv_bfloat16 g_Wphi[524288],  g_Wplo[524288];
__device__ __nv_bfloat16 g_Qhi[16777216], g_Qlo[16777216];
__device__ __nv_bfloat16 g_Khi[16777216], g_Klo[16777216];
__device__ __nv_bfloat16 g_Vhi[16777216], g_Vlo[16777216];
__device__ __nv_bfloat16 g_Vthi[16777216], g_Vtlo[16777216];     // V transposed [bh, e, t]
__device__ __nv_bfloat16 g_Phi[67108864], g_Plo[67108864];       // softmax probs split
__device__ __nv_bfloat16 g_Ohi[16777216], g_Olo[16777216];       // [B*S, H*D] concat layout

// ---------------- helpers ----------------
__device__ __forceinline__ uint32_t smem_u32(const void* p) {
    uint32_t a;
    asm("{ .reg .u64 t; cvta.to.shared.u64 t, %1; cvt.u32.u64 %0, t; }" : "=r"(a) : "l"(p));
    return a;
}

__device__ __forceinline__ void split_store2(float a, float b,
                                             __nv_bfloat16* dhi, __nv_bfloat16* dlo) {
    __nv_bfloat16 h0 = __float2bfloat16_rn(a), h1 = __float2bfloat16_rn(b);
    __nv_bfloat16 l0 = __float2bfloat16_rn(a - __bfloat162float(h0));
    __nv_bfloat16 l1 = __float2bfloat16_rn(b - __bfloat162float(h1));
    *(uint32_t*)dhi = (uint32_t)__bfloat16_as_ushort(h0) | ((uint32_t)__bfloat16_as_ushort(h1) << 16);
    *(uint32_t*)dlo = (uint32_t)__bfloat16_as_ushort(l0) | ((uint32_t)__bfloat16_as_ushort(l1) << 16);
}

__device__ __forceinline__ void split2(float a, float b, uint32_t& hi, uint32_t& lo) {
    __nv_bfloat16 h0 = __float2bfloat16_rn(a), h1 = __float2bfloat16_rn(b);
    __nv_bfloat16 l0 = __float2bfloat16_rn(a - __bfloat162float(h0));
    __nv_bfloat16 l1 = __float2bfloat16_rn(b - __bfloat162float(h1));
    hi = (uint32_t)__bfloat16_as_ushort(h0) | ((uint32_t)__bfloat16_as_ushort(h1) << 16);
    lo = (uint32_t)__bfloat16_as_ushort(l0) | ((uint32_t)__bfloat16_as_ushort(l1) << 16);
}

#define CP_ASYNC16(saddr, gptr) \
    asm volatile("cp.async.cg.shared.global [%0], [%1], 16;" :: "r"(saddr), "l"(gptr))
#define CP_COMMIT() asm volatile("cp.async.commit_group;")
#define CP_WAIT1()  asm volatile("cp.async.wait_group 1;")
#define CP_WAIT0()  asm volatile("cp.async.wait_group 0;")
#define LDMX4(r0, r1, r2, r3, addr) \
    asm volatile("ldmatrix.sync.aligned.m8n8.x4.shared.b16 {%0,%1,%2,%3}, [%4];" \
        : "=r"(r0), "=r"(r1), "=r"(r2), "=r"(r3) : "r"(addr))
#define MMA16816(acc, af, b0, b1) \
    asm volatile("mma.sync.aligned.m16n8k16.row.col.f32.bf16.bf16.f32 " \
        "{%0,%1,%2,%3}, {%4,%5,%6,%7}, {%8,%9}, {%0,%1,%2,%3};" \
        : "+f"((acc)[0]), "+f"((acc)[1]), "+f"((acc)[2]), "+f"((acc)[3]) \
        : "r"((af)[0]), "r"((af)[1]), "r"((af)[2]), "r"((af)[3]), "r"(b0), "r"(b1))

// ---------------------------------------------------------------------------
// 3-product single-sweep GEMM mainloop, templated on NF (B n-frags per warp).
// C[128, 32*NF] NT, fp32-split bf16: ahi*bhi + alo*bhi + ahi*blo per chunk.
// 8 warps 2(M) x 4(N); warp tile 64 x 8*NF.  BK=32.  3-stage cp.async
// pipeline, ONE __syncthreads per chunk, prefetch depth 2.
// Stage layout (bytes): sAh [128][40]bf16 @0 (10240), sAl @10240,
//   sBh [32*NF][40] @20480, sBl @20480+NF*2560.   stage = 20480 + NF*5120.
// ---------------------------------------------------------------------------
template<int NF>
__device__ __forceinline__ void mma_gemm3(
    const __nv_bfloat16* __restrict__ Ahi, const __nv_bfloat16* __restrict__ Alo,
    const __nv_bfloat16* __restrict__ Bhi, const __nv_bfloat16* __restrict__ Blo,
    int ldA, int ldB, int ksteps, float acc[4][NF][4], char* sm)
{
    constexpr int BROWS = 32 * NF;
    constexpr int BBYTES = BROWS * 80;
    constexpr int STAGE = 20480 + 2 * BBYTES;

    int t = threadIdx.x;
    int lane = t & 31, wid = t >> 5;
    int wm = wid & 1, wn = wid >> 1;

    #pragma unroll
    for (int mf = 0; mf < 4; mf++)
        #pragma unroll
        for (int nf = 0; nf < NF; nf++)
            #pragma unroll
            for (int e = 0; e < 4; e++) acc[mf][nf][e] = 0.f;

    auto load_tile = [&](int kc, int stg) {
        size_t kbase = (size_t)kc * 32;
        char* base = sm + stg * STAGE;
        #pragma unroll
        for (int i = 0; i < 1; i++) {        // A: 128 rows, 2 quads over 2 iters
            int idx = t;
            int row = idx >> 2, q = idx & 3;
            size_t aoff = (size_t)row * ldA + kbase + q * 8;
            uint32_t so = (uint32_t)(row * 80 + q * 16);
            CP_ASYNC16(smem_u32(base + so), Ahi + aoff);
            CP_ASYNC16(smem_u32(base + 10240 + so), Alo + aoff);
            int idx2 = t + 256;
            int row2 = idx2 >> 2, q2 = idx2 & 3;
            size_t aoff2 = (size_t)row2 * ldA + kbase + q2 * 8;
            uint32_t so2 = (uint32_t)(row2 * 80 + q2 * 16);
            CP_ASYNC16(smem_u32(base + so2), Ahi + aoff2);
            CP_ASYNC16(smem_u32(base + 10240 + so2), Alo + aoff2);
        }
        #pragma unroll
        for (int i = 0; i < NF / 2; i++) {   // B: 32*NF rows
            int idx = t + (i << 8);
            int row = idx >> 2, q = idx & 3;
            size_t boff = (size_t)row * ldB + kbase + q * 8;
            uint32_t so = (uint32_t)(row * 80 + q * 16);
            CP_ASYNC16(smem_u32(base + 20480 + so), Bhi + boff);
            CP_ASYNC16(smem_u32(base + 20480 + BBYTES + so), Blo + boff);
        }
        CP_COMMIT();
    };

    load_tile(0, 0);
    if (ksteps > 1) load_tile(1, 1);

    int stg = 0;
    for (int c = 0; c < ksteps; c++) {
        if (c + 1 < ksteps) { CP_WAIT1(); }
        else                { CP_WAIT0(); }
        __syncthreads();
        if (c + 2 < ksteps) {
            int ns = stg + 2; if (ns >= 3) ns -= 3;
            load_tile(c + 2, ns);
        }

        char* base = sm + stg * STAGE;
        #pragma unroll
        for (int k16 = 0; k16 < 2; k16++) {
            uint32_t afh[4][4], afl[4][4];
            #pragma unroll
            for (int mf = 0; mf < 4; mf++) {
                int row = wm * 64 + mf * 16 + (lane & 15);
                int ko  = k16 * 16 + (lane >> 4) * 8;
                uint32_t so = (uint32_t)(row * 80 + ko * 2);
                LDMX4(afh[mf][0], afh[mf][1], afh[mf][2], afh[mf][3], smem_u32(base + so));
                LDMX4(afl[mf][0], afl[mf][1], afl[mf][2], afl[mf][3], smem_u32(base + 10240 + so));
            }
            uint32_t bfh[NF][2], bfl[NF][2];
            #pragma unroll
            for (int p = 0; p < NF / 2; p++) {
                int nrow = wn * (8 * NF) + p * 16 + (lane & 7) + ((lane >> 4) << 3);
                int ko   = k16 * 16 + ((lane >> 3) & 1) * 8;
                uint32_t so = (uint32_t)(nrow * 80 + ko * 2);
                uint32_t r0, r1, r2, r3;
                LDMX4(r0, r1, r2, r3, smem_u32(base + 20480 + so));
                bfh[2*p][0] = r0; bfh[2*p][1] = r1;
                bfh[2*p+1][0] = r2; bfh[2*p+1][1] = r3;
                LDMX4(r0, r1, r2, r3, smem_u32(base + 20480 + BBYTES + so));
                bfl[2*p][0] = r0; bfl[2*p][1] = r1;
                bfl[2*p+1][0] = r2; bfl[2*p+1][1] = r3;
            }
            #pragma unroll
            for (int mf = 0; mf < 4; mf++)
                #pragma unroll
                for (int nf = 0; nf < NF; nf++) {
                    MMA16816(acc[mf][nf], afh[mf], bfh[nf][0], bfh[nf][1]);
                    MMA16816(acc[mf][nf], afl[mf], bfh[nf][0], bfh[nf][1]);
                    MMA16816(acc[mf][nf], afh[mf], bfl[nf][0], bfl[nf][1]);
                }
        }
        stg++; if (stg >= 3) stg = 0;
        __syncthreads();   // protect stage reuse: stage c%3 rewritten at c+3 prefetch
    }
}

#define SMEM_W (3 * (20480 + 2 * (256 * 80)))   // NF=8: 184320
#define SMEM_N (3 * (20480 + 2 * (128 * 80)))   // NF=4: 122880

// ---------------------------------------------------------------------------
// Kernel: split fp32 -> bf16 hi/lo
// ---------------------------------------------------------------------------
__global__ __launch_bounds__(256) void split_kernel(
    const float* __restrict__ src, __nv_bfloat16* __restrict__ hi,
    __nv_bfloat16* __restrict__ lo, int n4)
{
    int i = blockIdx.x * 256 + threadIdx.x;
    if (i >= n4) return;
    float4 v = *(const float4*)(src + 4 * (size_t)i);
    uint32_t ph[2], pl[2];
    split2(v.x, v.y, ph[0], pl[0]);
    split2(v.z, v.w, ph[1], pl[1]);
    *(uint2*)((char*)hi + 8 * (size_t)i) = make_uint2(ph[0], ph[1]);
    *(uint2*)((char*)lo + 8 * (size_t)i) = make_uint2(pl[0], pl[1]);
}

// ---------------------------------------------------------------------------
// Kernel: QKV projection (wide, N=256 in one block).  grid (8, 1, 192)
// Q pre-scaled by 2^-4 (exact) so scores needs no epilogue multiply.
// ---------------------------------------------------------------------------
__global__ __launch_bounds__(256) void qkv_g(
    const float* __restrict__ bq, const float* __restrict__ bk, const float* __restrict__ bv)
{
    extern __shared__ char sm[];
    int z = blockIdx.z, qkv = z >> 6, bh = z & 63, b = bh >> 3, h = bh & 7;
    int m0 = blockIdx.x * 128;

    const __nv_bfloat16* Whi = (qkv == 0) ? g_Wqhi : (qkv == 1) ? g_Wkhi : g_Wvhi;
    const __nv_bfloat16* Wlo = (qkv == 0) ? g_Wqlo : (qkv == 1) ? g_Wklo : g_Wvlo;
    const float* bias = ((qkv == 0) ? bq : (qkv == 1) ? bk : bv) + h * ND;

    float acc[4][8][4];
    mma_gemm3<8>(g_Xhi + ((size_t)b * NS + m0) * ND, g_Xlo + ((size_t)b * NS + m0) * ND,
                 Whi + (size_t)h * ND * ND, Wlo + (size_t)h * ND * ND,
                 ND, ND, 8, acc, sm);

    __nv_bfloat16* Ohi = (qkv == 0) ? g_Qhi : (qkv == 1) ? g_Khi : g_Vhi;
    __nv_bfloat16* Olo = (qkv == 0) ? g_Qlo : (qkv == 1) ? g_Klo : g_Vlo;
    float scale = (qkv == 0) ? 0.0625f : 1.0f;

    int lane = threadIdx.x & 31, wid = threadIdx.x >> 5;
    int wm = wid & 1, wn = wid >> 1;
    #pragma unroll
    for (int mf = 0; mf < 4; mf++) {
        int r = m0 + wm * 64 + mf * 16 + (lane >> 2);
        #pragma unroll
        for (int nf = 0; nf < 8; nf++) {
            int cc = wn * 64 + nf * 8 + ((lane & 3) << 1);
            float2 bb = *(const float2*)(bias + cc);
            size_t base0 = ((size_t)bh * NS + r) * ND + cc;
            size_t base1 = base0 + 8 * ND;
            split_store2((acc[mf][nf][0] + bb.x) * scale, (acc[mf][nf][1] + bb.y) * scale,
                         Ohi + base0, Olo + base0);
            split_store2((acc[mf][nf][2] + bb.x) * scale, (acc[mf][nf][3] + bb.y) * scale,
                         Ohi + base1, Olo + base1);
        }
    }
}

// ---------------------------------------------------------------------------
// Kernel: V transpose [bh,t,e] -> [bh,e,t] (hi+lo). grid (32, 8, 64), block (32,8)
// ---------------------------------------------------------------------------
__global__ void vt_kernel()
{
    __shared__ __nv_bfloat16 th[32][33], tl[32][33];
    int bh = blockIdx.z, t0 = blockIdx.x * 32, e0 = blockIdx.y * 32;
    int tx = threadIdx.x, ty = threadIdx.y;
    #pragma unroll
    for (int j = 0; j < 4; j++) {
        int rr = ty + j * 8;
        size_t idx = ((size_t)bh * NS + t0 + rr) * ND + e0 + tx;
        th[rr][tx] = g_Vhi[idx];
        tl[rr][tx] = g_Vlo[idx];
    }
    __syncthreads();
    #pragma unroll
    for (int j = 0; j < 4; j++) {
        int er = ty + j * 8;
        size_t idx = ((size_t)bh * ND + e0 + er) * NS + t0 + tx;
        g_Vthi[idx] = th[tx][er];
        g_Vtlo[idx] = tl[tx][er];
    }
}

// ---------------------------------------------------------------------------
// Kernel: scores = (Q/16) K^T (wide).  grid (8, 4, 64), n-tile 256
// ---------------------------------------------------------------------------
__global__ __launch_bounds__(256) void scores_g()
{
    extern __shared__ char sm[];
    int bh = blockIdx.z, m0 = blockIdx.x * 128, n0 = blockIdx.y * 256;
    float acc[4][8][4];
    mma_gemm3<8>(g_Qhi + ((size_t)bh * NS + m0) * ND, g_Qlo + ((size_t)bh * NS + m0) * ND,
                 g_Khi + ((size_t)bh * NS + n0) * ND, g_Klo + ((size_t)bh * NS + n0) * ND,
                 ND, ND, 8, acc, sm);

    int lane = threadIdx.x & 31, wid = threadIdx.x >> 5;
    int wm = wid & 1, wn = wid >> 1;
    #pragma unroll
    for (int mf = 0; mf < 4; mf++) {
        int r = m0 + wm * 64 + mf * 16 + (lane >> 2);
        #pragma unroll
        for (int nf = 0; nf < 8; nf++) {
            int cc = n0 + wn * 64 + nf * 8 + ((lane & 3) << 1);
            float* d0 = g_P + ((size_t)bh * NS + r) * NS + cc;
            *(float2*)d0 = make_float2(acc[mf][nf][0], acc[mf][nf][1]);
            *(float2*)(d0 + 8 * NS) = make_float2(acc[mf][nf][2], acc[mf][nf][3]);
        }
    }
}

// ---------------------------------------------------------------------------
// Kernel: softmax over keys + bf16 hi/lo split.  grid 65536, block 256
// ---------------------------------------------------------------------------
__global__ __launch_bounds__(256) void softmax_kernel()
{
    size_t rowoff = (size_t)blockIdx.x * NS;
    const float* p = g_P + rowoff;
    int t = threadIdx.x;
    float4 v = *(const float4*)(p + (t << 2));
    __shared__ float smx[8], ssm[8];

    float m = fmaxf(fmaxf(v.x, v.y), fmaxf(v.z, v.w));
    #pragma unroll
    for (int o = 16; o > 0; o >>= 1) m = fmaxf(m, __shfl_xor_sync(0xffffffffu, m, o));
    if ((t & 31) == 0) smx[t >> 5] = m;
    __syncthreads();
    if (t < 32) {
        float mm = (t < 8) ? smx[t] : -3.0e38f;
        #pragma unroll
        for (int o = 4; o > 0; o >>= 1) mm = fmaxf(mm, __shfl_xor_sync(0xffffffffu, mm, o));
        if (t == 0) smx[0] = mm;
    }
    __syncthreads();
    m = smx[0];
    v.x = __expf(v.x - m); v.y = __expf(v.y - m);
    v.z = __expf(v.z - m); v.w = __expf(v.w - m);
    float s = v.x + v.y + v.z + v.w;
    #pragma unroll
    for (int o = 16; o > 0; o >>= 1) s += __shfl_xor_sync(0xffffffffu, s, o);
    if ((t & 31) == 0) ssm[t >> 5] = s;
    __syncthreads();
    if (t < 32) {
        float sv = (t < 8) ? ssm[t] : 0.f;
        #pragma unroll
        for (int o = 4; o > 0; o >>= 1) sv += __shfl_xor_sync(0xffffffffu, sv, o);
        if (t == 0) ssm[0] = sv;
    }
    __syncthreads();
    float inv = 1.0f / ssm[0];
    float a[4] = {v.x * inv, v.y * inv, v.z * inv, v.w * inv};

    uint32_t ph[2], pl[2];
    split2(a[0], a[1], ph[0], pl[0]);
    split2(a[2], a[3], ph[1], pl[1]);
    *(uint2*)((char*)g_Phi + 2 * (rowoff + (t << 2))) = make_uint2(ph[0], ph[1]);
    *(uint2*)((char*)g_Plo + 2 * (rowoff + (t << 2))) = make_uint2(pl[0], pl[1]);
}

// ---------------------------------------------------------------------------
// Kernel: O = P @ V (wide, B = V^T, N=256 in one block).  grid (8, 1, 64)
// ---------------------------------------------------------------------------
__global__ __launch_bounds__(256) void pv_g()
{
    extern __shared__ char sm[];
    int bh = blockIdx.z, b = bh >> 3, h = bh & 7;
    int m0 = blockIdx.x * 128;
    float acc[4][8][4];
    mma_gemm3<8>(g_Phi + ((size_t)bh * NS + m0) * NS, g_Plo + ((size_t)bh * NS + m0) * NS,
                 g_Vthi + (size_t)bh * ND * NS, g_Vtlo + (size_t)bh * ND * NS,
                 NS, NS, 32, acc, sm);

    int lane = threadIdx.x & 31, wid = threadIdx.x >> 5;
    int wm = wid & 1, wn = wid >> 1;
    #pragma unroll
    for (int mf = 0; mf < 4; mf++) {
        int r = m0 + wm * 64 + mf * 16 + (lane >> 2);
        #pragma unroll
        for (int nf = 0; nf < 8; nf++) {
            int cc = wn * 64 + nf * 8 + ((lane & 3) << 1);
            size_t base0 = ((size_t)(b * NS + r)) * HD + h * ND + cc;
            size_t base1 = base0 + 8 * HD;
            split_store2(acc[mf][nf][0], acc[mf][nf][1], g_Ohi + base0, g_Olo + base0);
            split_store2(acc[mf][nf][2], acc[mf][nf][3], g_Ohi + base1, g_Olo + base1);
        }
    }
}

// ---------------------------------------------------------------------------
// Kernel: out = concat(O) @ Wp^T (narrow 128x128).  grid (64, 2, 1)
// ---------------------------------------------------------------------------
__global__ __launch_bounds__(256) void proj_g(float* __restrict__ out)
{
    extern __shared__ char sm[];
    int m0 = blockIdx.x * 128, n0 = blockIdx.y * 128;
    float acc[4][4][4];
    mma_gemm3<4>(g_Ohi + (size_t)m0 * HD, g_Olo + (size_t)m0 * HD,
                 g_Wphi + (size_t)n0 * HD, g_Wplo + (size_t)n0 * HD,
                 HD, HD, 64, acc, sm);

    int lane = threadIdx.x & 31, wid = threadIdx.x >> 5;
    int wm = wid & 1, wn = wid >> 1;
    #pragma unroll
    for (int mf = 0; mf < 4; mf++) {
        int r = m0 + wm * 64 + mf * 16 + (lane >> 2);
        #pragma unroll
        for (int nf = 0; nf < 4; nf++) {
            int cc = n0 + wn * 32 + nf * 8 + ((lane & 3) << 1);
            float* d0 = out + (size_t)r * ND + cc;
            *(float2*)d0 = make_float2(acc[mf][nf][0], acc[mf][nf][1]);
            *(float2*)(d0 + 8 * ND) = make_float2(acc[mf][nf][2], acc[mf][nf][3]);
        }
    }
}

// ---------------------------------------------------------------------------
extern "C" void kernel_launch(void* const* d_in, const int* in_sizes, int n_in,
                              void* d_out, int out_size)
{
    const float* x  = (const float*)d_in[0];
    const float* Wq = (const float*)d_in[1];
    const float* Wk = (const float*)d_in[2];
    const float* Wv = (const float*)d_in[3];
    const float* bq = (const float*)d_in[4];
    const float* bk = (const float*)d_in[5];
    const float* bv = (const float*)d_in[6];
    const float* Wp = (const float*)d_in[7];
    float* out = (float*)d_out;

    cudaFuncSetAttribute(qkv_g,    cudaFuncAttributeMaxDynamicSharedMemorySize, SMEM_W);
    cudaFuncSetAttribute(scores_g, cudaFuncAttributeMaxDynamicSharedMemorySize, SMEM_W);
    cudaFuncSetAttribute(pv_g,     cudaFuncAttributeMaxDynamicSharedMemorySize, SMEM_W);
    cudaFuncSetAttribute(proj_g,   cudaFuncAttributeMaxDynamicSharedMemorySize, SMEM_N);

    __nv_bfloat16 *Xhi, *Xlo, *Wqhi, *Wqlo, *Wkhi, *Wklo, *Wvhi, *Wvlo, *Wphi, *Wplo;
    cudaGetSymbolAddress((void**)&Xhi,  g_Xhi);  cudaGetSymbolAddress((void**)&Xlo,  g_Xlo);
    cudaGetSymbolAddress((void**)&Wqhi, g_Wqhi); cudaGetSymbolAddress((void**)&Wqlo, g_Wqlo);
    cudaGetSymbolAddress((void**)&Wkhi, g_Wkhi); cudaGetSymbolAddress((void**)&Wklo, g_Wklo);
    cudaGetSymbolAddress((void**)&Wvhi, g_Wvhi); cudaGetSymbolAddress((void**)&Wvlo, g_Wvlo);
    cudaGetSymbolAddress((void**)&Wphi, g_Wphi); cudaGetSymbolAddress((void**)&Wplo, g_Wplo);

    split_kernel<<<2048, 256>>>(x,  Xhi,  Xlo,  524288);
    split_kernel<<<512,  256>>>(Wq, Wqhi, Wqlo, 131072);
    split_kernel<<<512,  256>>>(Wk, Wkhi, Wklo, 131072);
    split_kernel<<<512,  256>>>(Wv, Wvhi, Wvlo, 131072);
    split_kernel<<<512,  256>>>(Wp, Wphi, Wplo, 131072);

    dim3 gq(8, 1, 192);
    qkv_g<<<gq, 256, SMEM_W>>>(bq, bk, bv);

    dim3 gt(32, 8, 64);
    vt_kernel<<<gt, dim3(32, 8)>>>();

    dim3 gs(8, 4, 64);
    scores_g<<<gs, 256, SMEM_W>>>();

    softmax_kernel<<<65536, 256>>>();

    dim3 gp(8, 1, 64);
    pv_g<<<gp, 256, SMEM_W>>>();

    dim3 go(64, 2, 1);
    proj_g<<<go, 256, SMEM_N>>>(out);
}

// round 9
// speedup vs baseline: 1.9693x; 1.3255x over previous
#include <cuda_runtime.h>
#include <cuda_fp16.h>
#include <cstdint>

#define NS 1024
#define ND 256
#define NH 8
#define HD 2048

// ---------------- scratch (static device memory; no allocs) ----------------
__device__ float g_P[67108864];                                   // 256 MB fp32 scores
__device__ __half g_Xhi[2097152],  g_Xlo[2097152];
__device__ __half g_Wqh[524288], g_Wkh[524288], g_Wvh[524288], g_Wph[524288];
__device__ __half g_Qhi[16777216], g_Qlo[16777216];
__device__ __half g_Khi[16777216];
__device__ __half g_Vhi[16777216];
__device__ __half g_Vth[16777216];                                // V transposed [bh, e, t]
__device__ __half g_Phi[67108864], g_Plo[67108864];               // softmax probs split
__device__ __half g_Ohi[16777216], g_Olo[16777216];               // [B*S, H*D] concat layout

// ---------------- helpers ----------------
__device__ __forceinline__ uint32_t smem_u32(const void* p) {
    uint32_t a;
    asm("{ .reg .u64 t; cvta.to.shared.u64 t, %1; cvt.u32.u64 %0, t; }" : "=r"(a) : "l"(p));
    return a;
}

__device__ __forceinline__ void split2h(float a, float b, uint32_t& hi, uint32_t& lo) {
    __half h0 = __float2half_rn(a), h1 = __float2half_rn(b);
    __half l0 = __float2half_rn(a - __half2float(h0));
    __half l1 = __float2half_rn(b - __half2float(h1));
    hi = (uint32_t)__half_as_ushort(h0) | ((uint32_t)__half_as_ushort(h1) << 16);
    lo = (uint32_t)__half_as_ushort(l0) | ((uint32_t)__half_as_ushort(l1) << 16);
}

__device__ __forceinline__ void split_store2h(float a, float b, __half* dhi, __half* dlo) {
    uint32_t hi, lo;
    split2h(a, b, hi, lo);
    *(uint32_t*)dhi = hi;
    *(uint32_t*)dlo = lo;
}

__device__ __forceinline__ uint32_t pack2h(float a, float b) {
    __half h0 = __float2half_rn(a), h1 = __float2half_rn(b);
    return (uint32_t)__half_as_ushort(h0) | ((uint32_t)__half_as_ushort(h1) << 16);
}

#define CP_ASYNC16(saddr, gptr) \
    asm volatile("cp.async.cg.shared.global [%0], [%1], 16;" :: "r"(saddr), "l"(gptr))
#define CP_COMMIT() asm volatile("cp.async.commit_group;")
#define CP_WAIT1()  asm volatile("cp.async.wait_group 1;")
#define CP_WAIT0()  asm volatile("cp.async.wait_group 0;")
#define LDMX4(r0, r1, r2, r3, addr) \
    asm volatile("ldmatrix.sync.aligned.m8n8.x4.shared.b16 {%0,%1,%2,%3}, [%4];" \
        : "=r"(r0), "=r"(r1), "=r"(r2), "=r"(r3) : "r"(addr))
#define MMA16816(acc, af, b0, b1) \
    asm volatile("mma.sync.aligned.m16n8k16.row.col.f32.f16.f16.f32 " \
        "{%0,%1,%2,%3}, {%4,%5,%6,%7}, {%8,%9}, {%0,%1,%2,%3};" \
        : "+f"((acc)[0]), "+f"((acc)[1]), "+f"((acc)[2]), "+f"((acc)[3]) \
        : "r"((af)[0]), "r"((af)[1]), "r"((af)[2]), "r"((af)[3]), "r"(b0), "r"(b1))

// ---------------------------------------------------------------------------
// 2-product single-sweep GEMM mainloop, templated on NF (B n-frags per warp).
// C[128, 32*NF] NT, fp32 via fp16 A-split: (ahi + alo) * bhi per chunk.
// Dropped term a*blo ~ 2^-12 relative.  8 warps 2(M) x 4(N); warp tile
// 64 x 8*NF.  BK=32.  3-stage cp.async pipeline, prefetch depth 2.
// Stage layout (bytes): sAh [128][40]h @0 (10240), sAl @10240,
//   sBh [32*NF][40]h @20480.   STAGE = 20480 + NF*2560.
// ---------------------------------------------------------------------------
template<int NF>
__device__ __forceinline__ void mma_gemm2(
    const __half* __restrict__ Ahi, const __half* __restrict__ Alo,
    const __half* __restrict__ Bhi,
    int ldA, int ldB, int ksteps, float acc[4][NF][4], char* sm)
{
    constexpr int BBYTES = 32 * NF * 80;
    constexpr int STAGE = 20480 + BBYTES;

    int t = threadIdx.x;
    int lane = t & 31, wid = t >> 5;
    int wm = wid & 1, wn = wid >> 1;

    #pragma unroll
    for (int mf = 0; mf < 4; mf++)
        #pragma unroll
        for (int nf = 0; nf < NF; nf++)
            #pragma unroll
            for (int e = 0; e < 4; e++) acc[mf][nf][e] = 0.f;

    auto load_tile = [&](int kc, int stg) {
        size_t kbase = (size_t)kc * 32;
        char* base = sm + stg * STAGE;
        {   // A: 128 rows x 4 quads = 512 positions, 2 per thread, hi+lo
            int row = t >> 2, q = t & 3;
            size_t aoff = (size_t)row * ldA + kbase + q * 8;
            uint32_t so = (uint32_t)(row * 80 + q * 16);
            CP_ASYNC16(smem_u32(base + so), Ahi + aoff);
            CP_ASYNC16(smem_u32(base + 10240 + so), Alo + aoff);
            int idx2 = t + 256;
            int row2 = idx2 >> 2, q2 = idx2 & 3;
            size_t aoff2 = (size_t)row2 * ldA + kbase + q2 * 8;
            uint32_t so2 = (uint32_t)(row2 * 80 + q2 * 16);
            CP_ASYNC16(smem_u32(base + so2), Ahi + aoff2);
            CP_ASYNC16(smem_u32(base + 10240 + so2), Alo + aoff2);
        }
        #pragma unroll
        for (int i = 0; i < NF / 2; i++) {   // B hi only: 32*NF rows
            int idx = t + (i << 8);
            int row = idx >> 2, q = idx & 3;
            size_t boff = (size_t)row * ldB + kbase + q * 8;
            uint32_t so = (uint32_t)(row * 80 + q * 16);
            CP_ASYNC16(smem_u32(base + 20480 + so), Bhi + boff);
        }
        CP_COMMIT();
    };

    load_tile(0, 0);
    if (ksteps > 1) load_tile(1, 1);

    int stg = 0;
    for (int c = 0; c < ksteps; c++) {
        if (c + 1 < ksteps) { CP_WAIT1(); }
        else                { CP_WAIT0(); }
        __syncthreads();
        if (c + 2 < ksteps) {
            int ns = stg + 2; if (ns >= 3) ns -= 3;
            load_tile(c + 2, ns);
        }

        char* base = sm + stg * STAGE;
        #pragma unroll
        for (int k16 = 0; k16 < 2; k16++) {
            uint32_t afh[4][4], afl[4][4];
            #pragma unroll
            for (int mf = 0; mf < 4; mf++) {
                int row = wm * 64 + mf * 16 + (lane & 15);
                int ko  = k16 * 16 + (lane >> 4) * 8;
                uint32_t so = (uint32_t)(row * 80 + ko * 2);
                LDMX4(afh[mf][0], afh[mf][1], afh[mf][2], afh[mf][3], smem_u32(base + so));
                LDMX4(afl[mf][0], afl[mf][1], afl[mf][2], afl[mf][3], smem_u32(base + 10240 + so));
            }
            uint32_t bf[NF][2];
            #pragma unroll
            for (int p = 0; p < NF / 2; p++) {
                int nrow = wn * (8 * NF) + p * 16 + (lane & 7) + ((lane >> 4) << 3);
                int ko   = k16 * 16 + ((lane >> 3) & 1) * 8;
                uint32_t so = (uint32_t)(nrow * 80 + ko * 2);
                uint32_t r0, r1, r2, r3;
                LDMX4(r0, r1, r2, r3, smem_u32(base + 20480 + so));
                bf[2*p][0] = r0; bf[2*p][1] = r1;
                bf[2*p+1][0] = r2; bf[2*p+1][1] = r3;
            }
            #pragma unroll
            for (int mf = 0; mf < 4; mf++)
                #pragma unroll
                for (int nf = 0; nf < NF; nf++) {
                    MMA16816(acc[mf][nf], afh[mf], bf[nf][0], bf[nf][1]);
                    MMA16816(acc[mf][nf], afl[mf], bf[nf][0], bf[nf][1]);
                }
        }
        stg++; if (stg >= 3) stg = 0;
        __syncthreads();
    }
}

#define SMEM_W (3 * (20480 + 8 * 2560))   // NF=8: 122880
#define SMEM_N (3 * (20480 + 4 * 2560))   // NF=4: 92160

// ---------------------------------------------------------------------------
// Kernel: split fp32 -> fp16 hi/lo  (A-side operands)
// ---------------------------------------------------------------------------
__global__ __launch_bounds__(256) void splitx_kernel(
    const float* __restrict__ src, __half* __restrict__ hi,
    __half* __restrict__ lo, int n4)
{
    int i = blockIdx.x * 256 + threadIdx.x;
    if (i >= n4) return;
    float4 v = *(const float4*)(src + 4 * (size_t)i);
    uint32_t ph[2], pl[2];
    split2h(v.x, v.y, ph[0], pl[0]);
    split2h(v.z, v.w, ph[1], pl[1]);
    *(uint2*)((char*)hi + 8 * (size_t)i) = make_uint2(ph[0], ph[1]);
    *(uint2*)((char*)lo + 8 * (size_t)i) = make_uint2(pl[0], pl[1]);
}

// Kernel: convert fp32 -> fp16 hi only (B-side operands)
__global__ __launch_bounds__(256) void cvt_kernel(
    const float* __restrict__ src, __half* __restrict__ hi, int n4)
{
    int i = blockIdx.x * 256 + threadIdx.x;
    if (i >= n4) return;
    float4 v = *(const float4*)(src + 4 * (size_t)i);
    *(uint2*)((char*)hi + 8 * (size_t)i) = make_uint2(pack2h(v.x, v.y), pack2h(v.z, v.w));
}

// ---------------------------------------------------------------------------
// Kernel: QKV projection (wide, N=256 in one block).  grid (8, 1, 192)
// Q pre-scaled by 2^-4 (exact); K/V store hi only (B-side operands).
// ---------------------------------------------------------------------------
__global__ __launch_bounds__(256) void qkv_g(
    const float* __restrict__ bq, const float* __restrict__ bk, const float* __restrict__ bv)
{
    extern __shared__ char sm[];
    int z = blockIdx.z, qkv = z >> 6, bh = z & 63, b = bh >> 3, h = bh & 7;
    int m0 = blockIdx.x * 128;

    const __half* Wh = (qkv == 0) ? g_Wqh : (qkv == 1) ? g_Wkh : g_Wvh;
    const float* bias = ((qkv == 0) ? bq : (qkv == 1) ? bk : bv) + h * ND;

    float acc[4][8][4];
    mma_gemm2<8>(g_Xhi + ((size_t)b * NS + m0) * ND, g_Xlo + ((size_t)b * NS + m0) * ND,
                 Wh + (size_t)h * ND * ND, ND, ND, 8, acc, sm);

    int lane = threadIdx.x & 31, wid = threadIdx.x >> 5;
    int wm = wid & 1, wn = wid >> 1;
    #pragma unroll
    for (int mf = 0; mf < 4; mf++) {
        int r = m0 + wm * 64 + mf * 16 + (lane >> 2);
        #pragma unroll
        for (int nf = 0; nf < 8; nf++) {
            int cc = wn * 64 + nf * 8 + ((lane & 3) << 1);
            float2 bb = *(const float2*)(bias + cc);
            float v0 = acc[mf][nf][0] + bb.x, v1 = acc[mf][nf][1] + bb.y;
            float v2 = acc[mf][nf][2] + bb.x, v3 = acc[mf][nf][3] + bb.y;
            size_t base0 = ((size_t)bh * NS + r) * ND + cc;
            size_t base1 = base0 + 8 * ND;
            if (qkv == 0) {
                split_store2h(v0 * 0.0625f, v1 * 0.0625f, g_Qhi + base0, g_Qlo + base0);
                split_store2h(v2 * 0.0625f, v3 * 0.0625f, g_Qhi + base1, g_Qlo + base1);
            } else if (qkv == 1) {
                *(uint32_t*)(g_Khi + base0) = pack2h(v0, v1);
                *(uint32_t*)(g_Khi + base1) = pack2h(v2, v3);
            } else {
                *(uint32_t*)(g_Vhi + base0) = pack2h(v0, v1);
                *(uint32_t*)(g_Vhi + base1) = pack2h(v2, v3);
            }
        }
    }
}

// ---------------------------------------------------------------------------
// Kernel: V transpose [bh,t,e] -> [bh,e,t] (hi only). grid (32, 8, 64), block (32,8)
// ---------------------------------------------------------------------------
__global__ void vt_kernel()
{
    __shared__ __half th[32][33];
    int bh = blockIdx.z, t0 = blockIdx.x * 32, e0 = blockIdx.y * 32;
    int tx = threadIdx.x, ty = threadIdx.y;
    #pragma unroll
    for (int j = 0; j < 4; j++) {
        int rr = ty + j * 8;
        th[rr][tx] = g_Vhi[((size_t)bh * NS + t0 + rr) * ND + e0 + tx];
    }
    __syncthreads();
    #pragma unroll
    for (int j = 0; j < 4; j++) {
        int er = ty + j * 8;
        g_Vth[((size_t)bh * ND + e0 + er) * NS + t0 + tx] = th[tx][er];
    }
}

// ---------------------------------------------------------------------------
// Kernel: scores = (Q/16) K^T (wide).  grid (8, 4, 64), n-tile 256
// ---------------------------------------------------------------------------
__global__ __launch_bounds__(256) void scores_g()
{
    extern __shared__ char sm[];
    int bh = blockIdx.z, m0 = blockIdx.x * 128, n0 = blockIdx.y * 256;
    float acc[4][8][4];
    mma_gemm2<8>(g_Qhi + ((size_t)bh * NS + m0) * ND, g_Qlo + ((size_t)bh * NS + m0) * ND,
                 g_Khi + ((size_t)bh * NS + n0) * ND, ND, ND, 8, acc, sm);

    int lane = threadIdx.x & 31, wid = threadIdx.x >> 5;
    int wm = wid & 1, wn = wid >> 1;
    #pragma unroll
    for (int mf = 0; mf < 4; mf++) {
        int r = m0 + wm * 64 + mf * 16 + (lane >> 2);
        #pragma unroll
        for (int nf = 0; nf < 8; nf++) {
            int cc = n0 + wn * 64 + nf * 8 + ((lane & 3) << 1);
            float* d0 = g_P + ((size_t)bh * NS + r) * NS + cc;
            *(float2*)d0 = make_float2(acc[mf][nf][0], acc[mf][nf][1]);
            *(float2*)(d0 + 8 * NS) = make_float2(acc[mf][nf][2], acc[mf][nf][3]);
        }
    }
}

// ---------------------------------------------------------------------------
// Kernel: softmax over keys + fp16 hi/lo split.  grid 65536, block 256
// ---------------------------------------------------------------------------
__global__ __launch_bounds__(256) void softmax_kernel()
{
    size_t rowoff = (size_t)blockIdx.x * NS;
    const float* p = g_P + rowoff;
    int t = threadIdx.x;
    float4 v = *(const float4*)(p + (t << 2));
    __shared__ float smx[8], ssm[8];

    float m = fmaxf(fmaxf(v.x, v.y), fmaxf(v.z, v.w));
    #pragma unroll
    for (int o = 16; o > 0; o >>= 1) m = fmaxf(m, __shfl_xor_sync(0xffffffffu, m, o));
    if ((t & 31) == 0) smx[t >> 5] = m;
    __syncthreads();
    if (t < 32) {
        float mm = (t < 8) ? smx[t] : -3.0e38f;
        #pragma unroll
        for (int o = 4; o > 0; o >>= 1) mm = fmaxf(mm, __shfl_xor_sync(0xffffffffu, mm, o));
        if (t == 0) smx[0] = mm;
    }
    __syncthreads();
    m = smx[0];
    v.x = __expf(v.x - m); v.y = __expf(v.y - m);
    v.z = __expf(v.z - m); v.w = __expf(v.w - m);
    float s = v.x + v.y + v.z + v.w;
    #pragma unroll
    for (int o = 16; o > 0; o >>= 1) s += __shfl_xor_sync(0xffffffffu, s, o);
    if ((t & 31) == 0) ssm[t >> 5] = s;
    __syncthreads();
    if (t < 32) {
        float sv = (t < 8) ? ssm[t] : 0.f;
        #pragma unroll
        for (int o = 4; o > 0; o >>= 1) sv += __shfl_xor_sync(0xffffffffu, sv, o);
        if (t == 0) ssm[0] = sv;
    }
    __syncthreads();
    float inv = 1.0f / ssm[0];

    uint32_t ph[2], pl[2];
    split2h(v.x * inv, v.y * inv, ph[0], pl[0]);
    split2h(v.z * inv, v.w * inv, ph[1], pl[1]);
    *(uint2*)((char*)g_Phi + 2 * (rowoff + (t << 2))) = make_uint2(ph[0], ph[1]);
    *(uint2*)((char*)g_Plo + 2 * (rowoff + (t << 2))) = make_uint2(pl[0], pl[1]);
}

// ---------------------------------------------------------------------------
// Kernel: O = P @ V (wide, B = V^T, N=256 in one block).  grid (8, 1, 64)
// ---------------------------------------------------------------------------
__global__ __launch_bounds__(256) void pv_g()
{
    extern __shared__ char sm[];
    int bh = blockIdx.z, b = bh >> 3, h = bh & 7;
    int m0 = blockIdx.x * 128;
    float acc[4][8][4];
    mma_gemm2<8>(g_Phi + ((size_t)bh * NS + m0) * NS, g_Plo + ((size_t)bh * NS + m0) * NS,
                 g_Vth + (size_t)bh * ND * NS, NS, NS, 32, acc, sm);

    int lane = threadIdx.x & 31, wid = threadIdx.x >> 5;
    int wm = wid & 1, wn = wid >> 1;
    #pragma unroll
    for (int mf = 0; mf < 4; mf++) {
        int r = m0 + wm * 64 + mf * 16 + (lane >> 2);
        #pragma unroll
        for (int nf = 0; nf < 8; nf++) {
            int cc = wn * 64 + nf * 8 + ((lane & 3) << 1);
            size_t base0 = ((size_t)(b * NS + r)) * HD + h * ND + cc;
            size_t base1 = base0 + 8 * HD;
            split_store2h(acc[mf][nf][0], acc[mf][nf][1], g_Ohi + base0, g_Olo + base0);
            split_store2h(acc[mf][nf][2], acc[mf][nf][3], g_Ohi + base1, g_Olo + base1);
        }
    }
}

// ---------------------------------------------------------------------------
// Kernel: out = concat(O) @ Wp^T (narrow 128x128).  grid (64, 2, 1)
// ---------------------------------------------------------------------------
__global__ __launch_bounds__(256) void proj_g(float* __restrict__ out)
{
    extern __shared__ char sm[];
    int m0 = blockIdx.x * 128, n0 = blockIdx.y * 128;
    float acc[4][4][4];
    mma_gemm2<4>(g_Ohi + (size_t)m0 * HD, g_Olo + (size_t)m0 * HD,
                 g_Wph + (size_t)n0 * HD, HD, HD, 64, acc, sm);

    int lane = threadIdx.x & 31, wid = threadIdx.x >> 5;
    int wm = wid & 1, wn = wid >> 1;
    #pragma unroll
    for (int mf = 0; mf < 4; mf++) {
        int r = m0 + wm * 64 + mf * 16 + (lane >> 2);
        #pragma unroll
        for (int nf = 0; nf < 4; nf++) {
            int cc = n0 + wn * 32 + nf * 8 + ((lane & 3) << 1);
            float* d0 = out + (size_t)r * ND + cc;
            *(float2*)d0 = make_float2(acc[mf][nf][0], acc[mf][nf][1]);
            *(float2*)(d0 + 8 * ND) = make_float2(acc[mf][nf][2], acc[mf][nf][3]);
        }
    }
}

// ---------------------------------------------------------------------------
extern "C" void kernel_launch(void* const* d_in, const int* in_sizes, int n_in,
                              void* d_out, int out_size)
{
    const float* x  = (const float*)d_in[0];
    const float* Wq = (const float*)d_in[1];
    const float* Wk = (const float*)d_in[2];
    const float* Wv = (const float*)d_in[3];
    const float* bq = (const float*)d_in[4];
    const float* bk = (const float*)d_in[5];
    const float* bv = (const float*)d_in[6];
    const float* Wp = (const float*)d_in[7];
    float* out = (float*)d_out;

    cudaFuncSetAttribute(qkv_g,    cudaFuncAttributeMaxDynamicSharedMemorySize, SMEM_W);
    cudaFuncSetAttribute(scores_g, cudaFuncAttributeMaxDynamicSharedMemorySize, SMEM_W);
    cudaFuncSetAttribute(pv_g,     cudaFuncAttributeMaxDynamicSharedMemorySize, SMEM_W);
    cudaFuncSetAttribute(proj_g,   cudaFuncAttributeMaxDynamicSharedMemorySize, SMEM_N);

    __half *Xhi, *Xlo, *Wqh, *Wkh, *Wvh, *Wph;
    cudaGetSymbolAddress((void**)&Xhi, g_Xhi); cudaGetSymbolAddress((void**)&Xlo, g_Xlo);
    cudaGetSymbolAddress((void**)&Wqh, g_Wqh); cudaGetSymbolAddress((void**)&Wkh, g_Wkh);
    cudaGetSymbolAddress((void**)&Wvh, g_Wvh); cudaGetSymbolAddress((void**)&Wph, g_Wph);

    splitx_kernel<<<2048, 256>>>(x, Xhi, Xlo, 524288);
    cvt_kernel<<<512, 256>>>(Wq, Wqh, 131072);
    cvt_kernel<<<512, 256>>>(Wk, Wkh, 131072);
    cvt_kernel<<<512, 256>>>(Wv, Wvh, 131072);
    cvt_kernel<<<512, 256>>>(Wp, Wph, 131072);

    dim3 gq(8, 1, 192);
    qkv_g<<<gq, 256, SMEM_W>>>(bq, bk, bv);

    dim3 gt(32, 8, 64);
    vt_kernel<<<gt, dim3(32, 8)>>>();

    dim3 gs(8, 4, 64);
    scores_g<<<gs, 256, SMEM_W>>>();

    softmax_kernel<<<65536, 256>>>();

    dim3 gp(8, 1, 64);
    pv_g<<<gp, 256, SMEM_W>>>();

    dim3 go(64, 2, 1);
    proj_g<<<go, 256, SMEM_N>>>(out);
}

// round 11
// speedup vs baseline: 2.7857x; 1.4146x over previous
#include <cuda_runtime.h>
#include <cuda_fp16.h>
#include <cstdint>

#define NS 1024
#define ND 256
#define NH 8
#define HD 2048

// ---------------- scratch (static device memory; no allocs) ----------------
__device__ float g_P[67108864];                                   // 256 MB fp32 scores
__device__ __half g_Xh[2097152];
__device__ __half g_Wqh[524288], g_Wkh[524288], g_Wvh[524288], g_Wph[524288];
__device__ __half g_Qh[16777216], g_Kh[16777216], g_Vh[16777216];
__device__ __half g_Vth[16777216];                                // V transposed [bh, e, t]
__device__ __half g_Ph[67108864];                                 // softmax probs fp16
__device__ __half g_Oh[16777216];                                 // [B*S, H*D] concat layout

// ---------------- helpers ----------------
__device__ __forceinline__ uint32_t smem_u32(const void* p) {
    uint32_t a;
    asm("{ .reg .u64 t; cvta.to.shared.u64 t, %1; cvt.u32.u64 %0, t; }" : "=r"(a) : "l"(p));
    return a;
}

__device__ __forceinline__ uint32_t pack2h(float a, float b) {
    __half h0 = __float2half_rn(a), h1 = __float2half_rn(b);
    return (uint32_t)__half_as_ushort(h0) | ((uint32_t)__half_as_ushort(h1) << 16);
}

#define CP_ASYNC16(saddr, gptr) \
    asm volatile("cp.async.cg.shared.global [%0], [%1], 16;" :: "r"(saddr), "l"(gptr))
#define CP_COMMIT() asm volatile("cp.async.commit_group;")
#define CP_WAIT1()  asm volatile("cp.async.wait_group 1;")
#define CP_WAIT0()  asm volatile("cp.async.wait_group 0;")
#define LDMX4(r0, r1, r2, r3, addr) \
    asm volatile("ldmatrix.sync.aligned.m8n8.x4.shared.b16 {%0,%1,%2,%3}, [%4];" \
        : "=r"(r0), "=r"(r1), "=r"(r2), "=r"(r3) : "r"(addr))
#define MMA16816(acc, af, b0, b1) \
    asm volatile("mma.sync.aligned.m16n8k16.row.col.f32.f16.f16.f32 " \
        "{%0,%1,%2,%3}, {%4,%5,%6,%7}, {%8,%9}, {%0,%1,%2,%3};" \
        : "+f"((acc)[0]), "+f"((acc)[1]), "+f"((acc)[2]), "+f"((acc)[3]) \
        : "r"((af)[0]), "r"((af)[1]), "r"((af)[2]), "r"((af)[3]), "r"(b0), "r"(b1))

// ---------------------------------------------------------------------------
// Single-product fp16 GEMM mainloop, templated on NF (B n-frags per warp).
// C[128, 32*NF] NT = A[128,K] * B[32NF,K]^T, fp32 accum.
// 8 warps 2(M) x 4(N); warp tile 64 x 8*NF.  BK=32.  3-stage cp.async
// pipeline, prefetch depth 2.
// Stage layout (bytes): sA [128][40]h @0 (10240), sB [32*NF][40]h @10240.
// STAGE = 10240 + NF*2560.
// ---------------------------------------------------------------------------
template<int NF>
__device__ __forceinline__ void mma_gemm1(
    const __half* __restrict__ A, const __half* __restrict__ B,
    int ldA, int ldB, int ksteps, float acc[4][NF][4], char* sm)
{
    constexpr int STAGE = 10240 + NF * 2560;

    int t = threadIdx.x;
    int lane = t & 31, wid = t >> 5;
    int wm = wid & 1, wn = wid >> 1;

    #pragma unroll
    for (int mf = 0; mf < 4; mf++)
        #pragma unroll
        for (int nf = 0; nf < NF; nf++)
            #pragma unroll
            for (int e = 0; e < 4; e++) acc[mf][nf][e] = 0.f;

    auto load_tile = [&](int kc, int stg) {
        size_t kbase = (size_t)kc * 32;
        char* base = sm + stg * STAGE;
        {   // A: 128 rows x 4 quads = 512 positions, 2 per thread
            int row = t >> 2, q = t & 3;
            CP_ASYNC16(smem_u32(base + row * 80 + q * 16),
                       A + (size_t)row * ldA + kbase + q * 8);
            int idx2 = t + 256;
            int row2 = idx2 >> 2, q2 = idx2 & 3;
            CP_ASYNC16(smem_u32(base + row2 * 80 + q2 * 16),
                       A + (size_t)row2 * ldA + kbase + q2 * 8);
        }
        #pragma unroll
        for (int i = 0; i < NF / 2; i++) {   // B: 32*NF rows x 4 quads
            int idx = t + (i << 8);
            int row = idx >> 2, q = idx & 3;
            CP_ASYNC16(smem_u32(base + 10240 + row * 80 + q * 16),
                       B + (size_t)row * ldB + kbase + q * 8);
        }
        CP_COMMIT();
    };

    load_tile(0, 0);
    if (ksteps > 1) load_tile(1, 1);

    int stg = 0;
    for (int c = 0; c < ksteps; c++) {
        if (c + 1 < ksteps) { CP_WAIT1(); }
        else                { CP_WAIT0(); }
        __syncthreads();
        if (c + 2 < ksteps) {
            int ns = stg + 2; if (ns >= 3) ns -= 3;
            load_tile(c + 2, ns);
        }

        char* base = sm + stg * STAGE;
        #pragma unroll
        for (int k16 = 0; k16 < 2; k16++) {
            uint32_t af[4][4];
            #pragma unroll
            for (int mf = 0; mf < 4; mf++) {
                int row = wm * 64 + mf * 16 + (lane & 15);
                int ko  = k16 * 16 + (lane >> 4) * 8;
                LDMX4(af[mf][0], af[mf][1], af[mf][2], af[mf][3],
                      smem_u32(base + row * 80 + ko * 2));
            }
            uint32_t bf[NF][2];
            #pragma unroll
            for (int p = 0; p < NF / 2; p++) {
                int nrow = wn * (8 * NF) + p * 16 + (lane & 7) + ((lane >> 4) << 3);
                int ko   = k16 * 16 + ((lane >> 3) & 1) * 8;
                uint32_t r0, r1, r2, r3;
                LDMX4(r0, r1, r2, r3, smem_u32(base + 10240 + nrow * 80 + ko * 2));
                bf[2*p][0] = r0; bf[2*p][1] = r1;
                bf[2*p+1][0] = r2; bf[2*p+1][1] = r3;
            }
            #pragma unroll
            for (int mf = 0; mf < 4; mf++)
                #pragma unroll
                for (int nf = 0; nf < NF; nf++)
                    MMA16816(acc[mf][nf], af[mf], bf[nf][0], bf[nf][1]);
        }
        stg++; if (stg >= 3) stg = 0;
        __syncthreads();
    }
}

#define SMEM_W (3 * (10240 + 8 * 2560))   // NF=8: 92160
#define SMEM_N (3 * (10240 + 4 * 2560))   // NF=4: 61440

// ---------------------------------------------------------------------------
// Kernel: convert fp32 -> fp16
// ---------------------------------------------------------------------------
__global__ __launch_bounds__(256) void cvt_kernel(
    const float* __restrict__ src, __half* __restrict__ dst, int n4)
{
    int i = blockIdx.x * 256 + threadIdx.x;
    if (i >= n4) return;
    float4 v = *(const float4*)(src + 4 * (size_t)i);
    *(uint2*)((char*)dst + 8 * (size_t)i) = make_uint2(pack2h(v.x, v.y), pack2h(v.z, v.w));
}

// ---------------------------------------------------------------------------
// Kernel: QKV projection (wide, N=256 in one block).  grid (8, 1, 192)
// Q pre-scaled by 2^-4 (exact).
// ---------------------------------------------------------------------------
__global__ __launch_bounds__(256) void qkv_g(
    const float* __restrict__ bq, const float* __restrict__ bk, const float* __restrict__ bv)
{
    extern __shared__ char sm[];
    int z = blockIdx.z, qkv = z >> 6, bh = z & 63, b = bh >> 3, h = bh & 7;
    int m0 = blockIdx.x * 128;

    const __half* Wh = (qkv == 0) ? g_Wqh : (qkv == 1) ? g_Wkh : g_Wvh;
    const float* bias = ((qkv == 0) ? bq : (qkv == 1) ? bk : bv) + h * ND;

    float acc[4][8][4];
    mma_gemm1<8>(g_Xh + ((size_t)b * NS + m0) * ND, Wh + (size_t)h * ND * ND,
                 ND, ND, 8, acc, sm);

    __half* Oh = (qkv == 0) ? g_Qh : (qkv == 1) ? g_Kh : g_Vh;
    float scale = (qkv == 0) ? 0.0625f : 1.0f;

    int lane = threadIdx.x & 31, wid = threadIdx.x >> 5;
    int wm = wid & 1, wn = wid >> 1;
    #pragma unroll
    for (int mf = 0; mf < 4; mf++) {
        int r = m0 + wm * 64 + mf * 16 + (lane >> 2);
        #pragma unroll
        for (int nf = 0; nf < 8; nf++) {
            int cc = wn * 64 + nf * 8 + ((lane & 3) << 1);
            float2 bb = *(const float2*)(bias + cc);
            size_t base0 = ((size_t)bh * NS + r) * ND + cc;
            size_t base1 = base0 + 8 * ND;
            *(uint32_t*)(Oh + base0) = pack2h((acc[mf][nf][0] + bb.x) * scale,
                                              (acc[mf][nf][1] + bb.y) * scale);
            *(uint32_t*)(Oh + base1) = pack2h((acc[mf][nf][2] + bb.x) * scale,
                                              (acc[mf][nf][3] + bb.y) * scale);
        }
    }
}

// ---------------------------------------------------------------------------
// Kernel: V transpose [bh,t,e] -> [bh,e,t]. grid (32, 8, 64), block (32,8)
// ---------------------------------------------------------------------------
__global__ void vt_kernel()
{
    __shared__ __half th[32][33];
    int bh = blockIdx.z, t0 = blockIdx.x * 32, e0 = blockIdx.y * 32;
    int tx = threadIdx.x, ty = threadIdx.y;
    #pragma unroll
    for (int j = 0; j < 4; j++) {
        int rr = ty + j * 8;
        th[rr][tx] = g_Vh[((size_t)bh * NS + t0 + rr) * ND + e0 + tx];
    }
    __syncthreads();
    #pragma unroll
    for (int j = 0; j < 4; j++) {
        int er = ty + j * 8;
        g_Vth[((size_t)bh * ND + e0 + er) * NS + t0 + tx] = th[tx][er];
    }
}

// ---------------------------------------------------------------------------
// Kernel: scores = (Q/16) K^T (wide).  grid (8, 4, 64), n-tile 256
// ---------------------------------------------------------------------------
__global__ __launch_bounds__(256) void scores_g()
{
    extern __shared__ char sm[];
    int bh = blockIdx.z, m0 = blockIdx.x * 128, n0 = blockIdx.y * 256;
    float acc[4][8][4];
    mma_gemm1<8>(g_Qh + ((size_t)bh * NS + m0) * ND,
                 g_Kh + ((size_t)bh * NS + n0) * ND, ND, ND, 8, acc, sm);

    int lane = threadIdx.x & 31, wid = threadIdx.x >> 5;
    int wm = wid & 1, wn = wid >> 1;
    #pragma unroll
    for (int mf = 0; mf < 4; mf++) {
        int r = m0 + wm * 64 + mf * 16 + (lane >> 2);
        #pragma unroll
        for (int nf = 0; nf < 8; nf++) {
            int cc = n0 + wn * 64 + nf * 8 + ((lane & 3) << 1);
            float* d0 = g_P + ((size_t)bh * NS + r) * NS + cc;
            *(float2*)d0 = make_float2(acc[mf][nf][0], acc[mf][nf][1]);
            *(float2*)(d0 + 8 * NS) = make_float2(acc[mf][nf][2], acc[mf][nf][3]);
        }
    }
}

// ---------------------------------------------------------------------------
// Kernel: softmax over keys -> fp16 probs.  grid 65536, block 256
// ---------------------------------------------------------------------------
__global__ __launch_bounds__(256) void softmax_kernel()
{
    size_t rowoff = (size_t)blockIdx.x * NS;
    const float* p = g_P + rowoff;
    int t = threadIdx.x;
    float4 v = *(const float4*)(p + (t << 2));
    __shared__ float smx[8], ssm[8];

    float m = fmaxf(fmaxf(v.x, v.y), fmaxf(v.z, v.w));
    #pragma unroll
    for (int o = 16; o > 0; o >>= 1) m = fmaxf(m, __shfl_xor_sync(0xffffffffu, m, o));
    if ((t & 31) == 0) smx[t >> 5] = m;
    __syncthreads();
    if (t < 32) {
        float mm = (t < 8) ? smx[t] : -3.0e38f;
        #pragma unroll
        for (int o = 4; o > 0; o >>= 1) mm = fmaxf(mm, __shfl_xor_sync(0xffffffffu, mm, o));
        if (t == 0) smx[0] = mm;
    }
    __syncthreads();
    m = smx[0];
    v.x = __expf(v.x - m); v.y = __expf(v.y - m);
    v.z = __expf(v.z - m); v.w = __expf(v.w - m);
    float s = v.x + v.y + v.z + v.w;
    #pragma unroll
    for (int o = 16; o > 0; o >>= 1) s += __shfl_xor_sync(0xffffffffu, s, o);
    if ((t & 31) == 0) ssm[t >> 5] = s;
    __syncthreads();
    if (t < 32) {
        float sv = (t < 8) ? ssm[t] : 0.f;
        #pragma unroll
        for (int o = 4; o > 0; o >>= 1) sv += __shfl_xor_sync(0xffffffffu, sv, o);
        if (t == 0) ssm[0] = sv;
    }
    __syncthreads();
    float inv = 1.0f / ssm[0];

    *(uint2*)((char*)g_Ph + 2 * (rowoff + (t << 2))) =
        make_uint2(pack2h(v.x * inv, v.y * inv), pack2h(v.z * inv, v.w * inv));
}

// ---------------------------------------------------------------------------
// Kernel: O = P @ V (wide, B = V^T, N=256 in one block).  grid (8, 1, 64)
// ---------------------------------------------------------------------------
__global__ __launch_bounds__(256) void pv_g()
{
    extern __shared__ char sm[];
    int bh = blockIdx.z, b = bh >> 3, h = bh & 7;
    int m0 = blockIdx.x * 128;
    float acc[4][8][4];
    mma_gemm1<8>(g_Ph + ((size_t)bh * NS + m0) * NS,
                 g_Vth + (size_t)bh * ND * NS, NS, NS, 32, acc, sm);

    int lane = threadIdx.x & 31, wid = threadIdx.x >> 5;
    int wm = wid & 1, wn = wid >> 1;
    #pragma unroll
    for (int mf = 0; mf < 4; mf++) {
        int r = m0 + wm * 64 + mf * 16 + (lane >> 2);
        #pragma unroll
        for (int nf = 0; nf < 8; nf++) {
            int cc = wn * 64 + nf * 8 + ((lane & 3) << 1);
            size_t base0 = ((size_t)(b * NS + r)) * HD + h * ND + cc;
            size_t base1 = base0 + 8 * HD;
            *(uint32_t*)(g_Oh + base0) = pack2h(acc[mf][nf][0], acc[mf][nf][1]);
            *(uint32_t*)(g_Oh + base1) = pack2h(acc[mf][nf][2], acc[mf][nf][3]);
        }
    }
}

// ---------------------------------------------------------------------------
// Kernel: out = concat(O) @ Wp^T (narrow 128x128).  grid (64, 2, 1)
// ---------------------------------------------------------------------------
__global__ __launch_bounds__(256) void proj_g(float* __restrict__ out)
{
    extern __shared__ char sm[];
    int m0 = blockIdx.x * 128, n0 = blockIdx.y * 128;
    float acc[4][4][4];
    mma_gemm1<4>(g_Oh + (size_t)m0 * HD, g_Wph + (size_t)n0 * HD,
                 HD, HD, 64, acc, sm);

    int lane = threadIdx.x & 31, wid = threadIdx.x >> 5;
    int wm = wid & 1, wn = wid >> 1;
    #pragma unroll
    for (int mf = 0; mf < 4; mf++) {
        int r = m0 + wm * 64 + mf * 16 + (lane >> 2);
        #pragma unroll
        for (int nf = 0; nf < 4; nf++) {
            int cc = n0 + wn * 32 + nf * 8 + ((lane & 3) << 1);
            float* d0 = out + (size_t)r * ND + cc;
            *(float2*)d0 = make_float2(acc[mf][nf][0], acc[mf][nf][1]);
            *(float2*)(d0 + 8 * ND) = make_float2(acc[mf][nf][2], acc[mf][nf][3]);
        }
    }
}

// ---------------------------------------------------------------------------
extern "C" void kernel_launch(void* const* d_in, const int* in_sizes, int n_in,
                              void* d_out, int out_size)
{
    const float* x  = (const float*)d_in[0];
    const float* Wq = (const float*)d_in[1];
    const float* Wk = (const float*)d_in[2];
    const float* Wv = (const float*)d_in[3];
    const float* bq = (const float*)d_in[4];
    const float* bk = (const float*)d_in[5];
    const float* bv = (const float*)d_in[6];
    const float* Wp = (const float*)d_in[7];
    float* out = (float*)d_out;

    cudaFuncSetAttribute(qkv_g,    cudaFuncAttributeMaxDynamicSharedMemorySize, SMEM_W);
    cudaFuncSetAttribute(scores_g, cudaFuncAttributeMaxDynamicSharedMemorySize, SMEM_W);
    cudaFuncSetAttribute(pv_g,     cudaFuncAttributeMaxDynamicSharedMemorySize, SMEM_W);
    cudaFuncSetAttribute(proj_g,   cudaFuncAttributeMaxDynamicSharedMemorySize, SMEM_N);

    __half *Xh, *Wqh, *Wkh, *Wvh, *Wph;
    cudaGetSymbolAddress((void**)&Xh,  g_Xh);
    cudaGetSymbolAddress((void**)&Wqh, g_Wqh); cudaGetSymbolAddress((void**)&Wkh, g_Wkh);
    cudaGetSymbolAddress((void**)&Wvh, g_Wvh); cudaGetSymbolAddress((void**)&Wph, g_Wph);

    cvt_kernel<<<2048, 256>>>(x,  Xh,  524288);
    cvt_kernel<<<512,  256>>>(Wq, Wqh, 131072);
    cvt_kernel<<<512,  256>>>(Wk, Wkh, 131072);
    cvt_kernel<<<512,  256>>>(Wv, Wvh, 131072);
    cvt_kernel<<<512,  256>>>(Wp, Wph, 131072);

    dim3 gq(8, 1, 192);
    qkv_g<<<gq, 256, SMEM_W>>>(bq, bk, bv);

    dim3 gt(32, 8, 64);
    vt_kernel<<<gt, dim3(32, 8)>>>();

    dim3 gs(8, 4, 64);
    scores_g<<<gs, 256, SMEM_W>>>();

    softmax_kernel<<<65536, 256>>>();

    dim3 gp(8, 1, 64);
    pv_g<<<gp, 256, SMEM_W>>>();

    dim3 go(64, 2, 1);
    proj_g<<<go, 256, SMEM_N>>>(out);
}

// round 12
// speedup vs baseline: 2.8624x; 1.0275x over previous
#include <cuda_runtime.h>
#include <cuda_fp16.h>
#include <cstdint>

#define NS 1024
#define ND 256
#define NH 8
#define HD 2048

// ---------------- scratch (static device memory; no allocs) ----------------
__device__ __half g_Xh[2097152];
__device__ __half g_Wqh[524288], g_Wkh[524288], g_Wvh[524288], g_Wph[524288];
__device__ __half g_Qh[16777216], g_Kh[16777216], g_Vh[16777216];
__device__ __half g_Vth[16777216];                                // V transposed [bh, e, t]
__device__ __half g_Ph[67108864];                                 // fp16 logits -> probs (in place)
__device__ __half g_Oh[16777216];                                 // [B*S, H*D] concat layout

// ---------------- helpers ----------------
__device__ __forceinline__ uint32_t smem_u32(const void* p) {
    uint32_t a;
    asm("{ .reg .u64 t; cvta.to.shared.u64 t, %1; cvt.u32.u64 %0, t; }" : "=r"(a) : "l"(p));
    return a;
}

__device__ __forceinline__ uint32_t pack2h(float a, float b) {
    __half h0 = __float2half_rn(a), h1 = __float2half_rn(b);
    return (uint32_t)__half_as_ushort(h0) | ((uint32_t)__half_as_ushort(h1) << 16);
}

#define CP_ASYNC16(saddr, gptr) \
    asm volatile("cp.async.cg.shared.global [%0], [%1], 16;" :: "r"(saddr), "l"(gptr))
#define CP_COMMIT() asm volatile("cp.async.commit_group;")
#define CP_WAIT1()  asm volatile("cp.async.wait_group 1;")
#define CP_WAIT0()  asm volatile("cp.async.wait_group 0;")
#define LDMX4(r0, r1, r2, r3, addr) \
    asm volatile("ldmatrix.sync.aligned.m8n8.x4.shared.b16 {%0,%1,%2,%3}, [%4];" \
        : "=r"(r0), "=r"(r1), "=r"(r2), "=r"(r3) : "r"(addr))
#define MMA16816(acc, af, b0, b1) \
    asm volatile("mma.sync.aligned.m16n8k16.row.col.f32.f16.f16.f32 " \
        "{%0,%1,%2,%3}, {%4,%5,%6,%7}, {%8,%9}, {%0,%1,%2,%3};" \
        : "+f"((acc)[0]), "+f"((acc)[1]), "+f"((acc)[2]), "+f"((acc)[3]) \
        : "r"((af)[0]), "r"((af)[1]), "r"((af)[2]), "r"((af)[3]), "r"(b0), "r"(b1))

// ---------------------------------------------------------------------------
// Single-product fp16 GEMM mainloop, templated on NF (B n-frags per warp).
// C[128, 32*NF] NT = A[128,K] * B[32NF,K]^T, fp32 accum.
// 8 warps 2(M) x 4(N); warp tile 64 x 8*NF.  BK=32.  3-stage cp.async
// pipeline, prefetch depth 2.
// Stage layout (bytes): sA [128][40]h @0 (10240), sB [32*NF][40]h @10240.
// STAGE = 10240 + NF*2560.
// ---------------------------------------------------------------------------
template<int NF>
__device__ __forceinline__ void mma_gemm1(
    const __half* __restrict__ A, const __half* __restrict__ B,
    int ldA, int ldB, int ksteps, float acc[4][NF][4], char* sm)
{
    constexpr int STAGE = 10240 + NF * 2560;

    int t = threadIdx.x;
    int lane = t & 31, wid = t >> 5;
    int wm = wid & 1, wn = wid >> 1;

    #pragma unroll
    for (int mf = 0; mf < 4; mf++)
        #pragma unroll
        for (int nf = 0; nf < NF; nf++)
            #pragma unroll
            for (int e = 0; e < 4; e++) acc[mf][nf][e] = 0.f;

    auto load_tile = [&](int kc, int stg) {
        size_t kbase = (size_t)kc * 32;
        char* base = sm + stg * STAGE;
        {   // A: 128 rows x 4 quads = 512 positions, 2 per thread
            int row = t >> 2, q = t & 3;
            CP_ASYNC16(smem_u32(base + row * 80 + q * 16),
                       A + (size_t)row * ldA + kbase + q * 8);
            int idx2 = t + 256;
            int row2 = idx2 >> 2, q2 = idx2 & 3;
            CP_ASYNC16(smem_u32(base + row2 * 80 + q2 * 16),
                       A + (size_t)row2 * ldA + kbase + q2 * 8);
        }
        #pragma unroll
        for (int i = 0; i < NF / 2; i++) {   // B: 32*NF rows x 4 quads
            int idx = t + (i << 8);
            int row = idx >> 2, q = idx & 3;
            CP_ASYNC16(smem_u32(base + 10240 + row * 80 + q * 16),
                       B + (size_t)row * ldB + kbase + q * 8);
        }
        CP_COMMIT();
    };

    load_tile(0, 0);
    if (ksteps > 1) load_tile(1, 1);

    int stg = 0;
    for (int c = 0; c < ksteps; c++) {
        if (c + 1 < ksteps) { CP_WAIT1(); }
        else                { CP_WAIT0(); }
        __syncthreads();
        if (c + 2 < ksteps) {
            int ns = stg + 2; if (ns >= 3) ns -= 3;
            load_tile(c + 2, ns);
        }

        char* base = sm + stg * STAGE;
        #pragma unroll
        for (int k16 = 0; k16 < 2; k16++) {
            uint32_t af[4][4];
            #pragma unroll
            for (int mf = 0; mf < 4; mf++) {
                int row = wm * 64 + mf * 16 + (lane & 15);
                int ko  = k16 * 16 + (lane >> 4) * 8;
                LDMX4(af[mf][0], af[mf][1], af[mf][2], af[mf][3],
                      smem_u32(base + row * 80 + ko * 2));
            }
            uint32_t bf[NF][2];
            #pragma unroll
            for (int p = 0; p < NF / 2; p++) {
                int nrow = wn * (8 * NF) + p * 16 + (lane & 7) + ((lane >> 4) << 3);
                int ko   = k16 * 16 + ((lane >> 3) & 1) * 8;
                uint32_t r0, r1, r2, r3;
                LDMX4(r0, r1, r2, r3, smem_u32(base + 10240 + nrow * 80 + ko * 2));
                bf[2*p][0] = r0; bf[2*p][1] = r1;
                bf[2*p+1][0] = r2; bf[2*p+1][1] = r3;
            }
            #pragma unroll
            for (int mf = 0; mf < 4; mf++)
                #pragma unroll
                for (int nf = 0; nf < NF; nf++)
                    MMA16816(acc[mf][nf], af[mf], bf[nf][0], bf[nf][1]);
        }
        stg++; if (stg >= 3) stg = 0;
        __syncthreads();
    }
}

#define SMEM_W (3 * (10240 + 8 * 2560))   // NF=8: 92160
#define SMEM_N (3 * (10240 + 4 * 2560))   // NF=4: 61440

// ---------------------------------------------------------------------------
// Kernel: fused fp32 -> fp16 convert for all 5 inputs.  grid 4096, block 256
// blocks [0,2048): X;  [2048,2560): Wq;  [2560,3072): Wk;
// blocks [3072,3584): Wv;  [3584,4096): Wp
// ---------------------------------------------------------------------------
__global__ __launch_bounds__(256) void cvt_all(
    const float* __restrict__ x,  const float* __restrict__ Wq,
    const float* __restrict__ Wk, const float* __restrict__ Wv,
    const float* __restrict__ Wp)
{
    int blk = blockIdx.x;
    const float* src;
    __half* dst;
    int local;
    if (blk < 2048)      { src = x;  dst = g_Xh;  local = blk; }
    else if (blk < 2560) { src = Wq; dst = g_Wqh; local = blk - 2048; }
    else if (blk < 3072) { src = Wk; dst = g_Wkh; local = blk - 2560; }
    else if (blk < 3584) { src = Wv; dst = g_Wvh; local = blk - 3072; }
    else                 { src = Wp; dst = g_Wph; local = blk - 3584; }
    int i = local * 256 + threadIdx.x;
    float4 v = *(const float4*)(src + 4 * (size_t)i);
    *(uint2*)((char*)dst + 8 * (size_t)i) = make_uint2(pack2h(v.x, v.y), pack2h(v.z, v.w));
}

// ---------------------------------------------------------------------------
// Kernel: QKV projection (wide, N=256 in one block).  grid (8, 1, 192)
// Q pre-scaled by 2^-4 (exact).
// ---------------------------------------------------------------------------
__global__ __launch_bounds__(256) void qkv_g(
    const float* __restrict__ bq, const float* __restrict__ bk, const float* __restrict__ bv)
{
    extern __shared__ char sm[];
    int z = blockIdx.z, qkv = z >> 6, bh = z & 63, b = bh >> 3, h = bh & 7;
    int m0 = blockIdx.x * 128;

    const __half* Wh = (qkv == 0) ? g_Wqh : (qkv == 1) ? g_Wkh : g_Wvh;
    const float* bias = ((qkv == 0) ? bq : (qkv == 1) ? bk : bv) + h * ND;

    float acc[4][8][4];
    mma_gemm1<8>(g_Xh + ((size_t)b * NS + m0) * ND, Wh + (size_t)h * ND * ND,
                 ND, ND, 8, acc, sm);

    __half* Oh = (qkv == 0) ? g_Qh : (qkv == 1) ? g_Kh : g_Vh;
    float scale = (qkv == 0) ? 0.0625f : 1.0f;

    int lane = threadIdx.x & 31, wid = threadIdx.x >> 5;
    int wm = wid & 1, wn = wid >> 1;
    #pragma unroll
    for (int mf = 0; mf < 4; mf++) {
        int r = m0 + wm * 64 + mf * 16 + (lane >> 2);
        #pragma unroll
        for (int nf = 0; nf < 8; nf++) {
            int cc = wn * 64 + nf * 8 + ((lane & 3) << 1);
            float2 bb = *(const float2*)(bias + cc);
            size_t base0 = ((size_t)bh * NS + r) * ND + cc;
            size_t base1 = base0 + 8 * ND;
            *(uint32_t*)(Oh + base0) = pack2h((acc[mf][nf][0] + bb.x) * scale,
                                              (acc[mf][nf][1] + bb.y) * scale);
            *(uint32_t*)(Oh + base1) = pack2h((acc[mf][nf][2] + bb.x) * scale,
                                              (acc[mf][nf][3] + bb.y) * scale);
        }
    }
}

// ---------------------------------------------------------------------------
// Kernel: V transpose [bh,t,e] -> [bh,e,t]. grid (32, 8, 64), block (32,8)
// ---------------------------------------------------------------------------
__global__ void vt_kernel()
{
    __shared__ __half th[32][33];
    int bh = blockIdx.z, t0 = blockIdx.x * 32, e0 = blockIdx.y * 32;
    int tx = threadIdx.x, ty = threadIdx.y;
    #pragma unroll
    for (int j = 0; j < 4; j++) {
        int rr = ty + j * 8;
        th[rr][tx] = g_Vh[((size_t)bh * NS + t0 + rr) * ND + e0 + tx];
    }
    __syncthreads();
    #pragma unroll
    for (int j = 0; j < 4; j++) {
        int er = ty + j * 8;
        g_Vth[((size_t)bh * ND + e0 + er) * NS + t0 + tx] = th[tx][er];
    }
}

// ---------------------------------------------------------------------------
// Kernel: scores = (Q/16) K^T -> fp16 logits.  grid (8, 4, 64), n-tile 256
// ---------------------------------------------------------------------------
__global__ __launch_bounds__(256) void scores_g()
{
    extern __shared__ char sm[];
    int bh = blockIdx.z, m0 = blockIdx.x * 128, n0 = blockIdx.y * 256;
    float acc[4][8][4];
    mma_gemm1<8>(g_Qh + ((size_t)bh * NS + m0) * ND,
                 g_Kh + ((size_t)bh * NS + n0) * ND, ND, ND, 8, acc, sm);

    int lane = threadIdx.x & 31, wid = threadIdx.x >> 5;
    int wm = wid & 1, wn = wid >> 1;
    #pragma unroll
    for (int mf = 0; mf < 4; mf++) {
        int r = m0 + wm * 64 + mf * 16 + (lane >> 2);
        #pragma unroll
        for (int nf = 0; nf < 8; nf++) {
            int cc = n0 + wn * 64 + nf * 8 + ((lane & 3) << 1);
            __half* d0 = g_Ph + ((size_t)bh * NS + r) * NS + cc;
            *(uint32_t*)d0 = pack2h(acc[mf][nf][0], acc[mf][nf][1]);
            *(uint32_t*)(d0 + 8 * NS) = pack2h(acc[mf][nf][2], acc[mf][nf][3]);
        }
    }
}

// ---------------------------------------------------------------------------
// Kernel: in-place softmax over keys on fp16 logits.  grid 65536, block 256
// ---------------------------------------------------------------------------
__global__ __launch_bounds__(256) void softmax_kernel()
{
    size_t rowoff = (size_t)blockIdx.x * NS;
    int t = threadIdx.x;
    uint2 raw = *(uint2*)((char*)g_Ph + 2 * (rowoff + (t << 2)));
    __half2 h01 = *(__half2*)&raw.x, h23 = *(__half2*)&raw.y;
    float2 f01 = __half22float2(h01), f23 = __half22float2(h23);
    float4 v = make_float4(f01.x, f01.y, f23.x, f23.y);
    __shared__ float smx[8], ssm[8];

    float m = fmaxf(fmaxf(v.x, v.y), fmaxf(v.z, v.w));
    #pragma unroll
    for (int o = 16; o > 0; o >>= 1) m = fmaxf(m, __shfl_xor_sync(0xffffffffu, m, o));
    if ((t & 31) == 0) smx[t >> 5] = m;
    __syncthreads();
    if (t < 32) {
        float mm = (t < 8) ? smx[t] : -3.0e38f;
        #pragma unroll
        for (int o = 4; o > 0; o >>= 1) mm = fmaxf(mm, __shfl_xor_sync(0xffffffffu, mm, o));
        if (t == 0) smx[0] = mm;
    }
    __syncthreads();
    m = smx[0];
    v.x = __expf(v.x - m); v.y = __expf(v.y - m);
    v.z = __expf(v.z - m); v.w = __expf(v.w - m);
    float s = v.x + v.y + v.z + v.w;
    #pragma unroll
    for (int o = 16; o > 0; o >>= 1) s += __shfl_xor_sync(0xffffffffu, s, o);
    if ((t & 31) == 0) ssm[t >> 5] = s;
    __syncthreads();
    if (t < 32) {
        float sv = (t < 8) ? ssm[t] : 0.f;
        #pragma unroll
        for (int o = 4; o > 0; o >>= 1) sv += __shfl_xor_sync(0xffffffffu, sv, o);
        if (t == 0) ssm[0] = sv;
    }
    __syncthreads();
    float inv = 1.0f / ssm[0];

    *(uint2*)((char*)g_Ph + 2 * (rowoff + (t << 2))) =
        make_uint2(pack2h(v.x * inv, v.y * inv), pack2h(v.z * inv, v.w * inv));
}

// ---------------------------------------------------------------------------
// Kernel: O = P @ V (wide, B = V^T, N=256 in one block).  grid (8, 1, 64)
// ---------------------------------------------------------------------------
__global__ __launch_bounds__(256) void pv_g()
{
    extern __shared__ char sm[];
    int bh = blockIdx.z, b = bh >> 3, h = bh & 7;
    int m0 = blockIdx.x * 128;
    float acc[4][8][4];
    mma_gemm1<8>(g_Ph + ((size_t)bh * NS + m0) * NS,
                 g_Vth + (size_t)bh * ND * NS, NS, NS, 32, acc, sm);

    int lane = threadIdx.x & 31, wid = threadIdx.x >> 5;
    int wm = wid & 1, wn = wid >> 1;
    #pragma unroll
    for (int mf = 0; mf < 4; mf++) {
        int r = m0 + wm * 64 + mf * 16 + (lane >> 2);
        #pragma unroll
        for (int nf = 0; nf < 8; nf++) {
            int cc = wn * 64 + nf * 8 + ((lane & 3) << 1);
            size_t base0 = ((size_t)(b * NS + r)) * HD + h * ND + cc;
            size_t base1 = base0 + 8 * HD;
            *(uint32_t*)(g_Oh + base0) = pack2h(acc[mf][nf][0], acc[mf][nf][1]);
            *(uint32_t*)(g_Oh + base1) = pack2h(acc[mf][nf][2], acc[mf][nf][3]);
        }
    }
}

// ---------------------------------------------------------------------------
// Kernel: out = concat(O) @ Wp^T (narrow 128x128).  grid (64, 2, 1)
// ---------------------------------------------------------------------------
__global__ __launch_bounds__(256) void proj_g(float* __restrict__ out)
{
    extern __shared__ char sm[];
    int m0 = blockIdx.x * 128, n0 = blockIdx.y * 128;
    float acc[4][4][4];
    mma_gemm1<4>(g_Oh + (size_t)m0 * HD, g_Wph + (size_t)n0 * HD,
                 HD, HD, 64, acc, sm);

    int lane = threadIdx.x & 31, wid = threadIdx.x >> 5;
    int wm = wid & 1, wn = wid >> 1;
    #pragma unroll
    for (int mf = 0; mf < 4; mf++) {
        int r = m0 + wm * 64 + mf * 16 + (lane >> 2);
        #pragma unroll
        for (int nf = 0; nf < 4; nf++) {
            int cc = n0 + wn * 32 + nf * 8 + ((lane & 3) << 1);
            float* d0 = out + (size_t)r * ND + cc;
            *(float2*)d0 = make_float2(acc[mf][nf][0], acc[mf][nf][1]);
            *(float2*)(d0 + 8 * ND) = make_float2(acc[mf][nf][2], acc[mf][nf][3]);
        }
    }
}

// ---------------------------------------------------------------------------
extern "C" void kernel_launch(void* const* d_in, const int* in_sizes, int n_in,
                              void* d_out, int out_size)
{
    const float* x  = (const float*)d_in[0];
    const float* Wq = (const float*)d_in[1];
    const float* Wk = (const float*)d_in[2];
    const float* Wv = (const float*)d_in[3];
    const float* bq = (const float*)d_in[4];
    const float* bk = (const float*)d_in[5];
    const float* bv = (const float*)d_in[6];
    const float* Wp = (const float*)d_in[7];
    float* out = (float*)d_out;

    cudaFuncSetAttribute(qkv_g,    cudaFuncAttributeMaxDynamicSharedMemorySize, SMEM_W);
    cudaFuncSetAttribute(scores_g, cudaFuncAttributeMaxDynamicSharedMemorySize, SMEM_W);
    cudaFuncSetAttribute(pv_g,     cudaFuncAttributeMaxDynamicSharedMemorySize, SMEM_W);
    cudaFuncSetAttribute(proj_g,   cudaFuncAttributeMaxDynamicSharedMemorySize, SMEM_N);

    cvt_all<<<4096, 256>>>(x, Wq, Wk, Wv, Wp);

    dim3 gq(8, 1, 192);
    qkv_g<<<gq, 256, SMEM_W>>>(bq, bk, bv);

    dim3 gt(32, 8, 64);
    vt_kernel<<<gt, dim3(32, 8)>>>();

    dim3 gs(8, 4, 64);
    scores_g<<<gs, 256, SMEM_W>>>();

    softmax_kernel<<<65536, 256>>>();

    dim3 gp(8, 1, 64);
    pv_g<<<gp, 256, SMEM_W>>>();

    dim3 go(64, 2, 1);
    proj_g<<<go, 256, SMEM_N>>>(out);
}

// round 13
// speedup vs baseline: 3.3892x; 1.1840x over previous
#include <cuda_runtime.h>
#include <cuda_fp16.h>
#include <cstdint>

#define NS 1024
#define ND 256
#define NH 8
#define HD 2048

// ---------------- scratch (static device memory; no allocs) ----------------
__device__ __half g_Xh[2097152];
__device__ __half g_Wqh[524288], g_Wkh[524288], g_Wvh[524288], g_Wph[524288];
__device__ __half g_Qh[16777216], g_Kh[16777216], g_Vh[16777216];
__device__ __half g_Vth[16777216];                                // V transposed [bh, e, t]
__device__ __half g_Ph[67108864];                                 // fp16 logits -> probs (in place)
__device__ __half g_Oh[16777216];                                 // [B*S, H*D] concat layout

// ---------------- helpers ----------------
__device__ __forceinline__ uint32_t smem_u32(const void* p) {
    uint32_t a;
    asm("{ .reg .u64 t; cvta.to.shared.u64 t, %1; cvt.u32.u64 %0, t; }" : "=r"(a) : "l"(p));
    return a;
}

__device__ __forceinline__ uint32_t pack2h(float a, float b) {
    __half h0 = __float2half_rn(a), h1 = __float2half_rn(b);
    return (uint32_t)__half_as_ushort(h0) | ((uint32_t)__half_as_ushort(h1) << 16);
}

#define CP_ASYNC16(saddr, gptr) \
    asm volatile("cp.async.cg.shared.global [%0], [%1], 16;" :: "r"(saddr), "l"(gptr))
#define CP_COMMIT() asm volatile("cp.async.commit_group;")
#define CP_WAIT1()  asm volatile("cp.async.wait_group 1;")
#define CP_WAIT0()  asm volatile("cp.async.wait_group 0;")
#define LDMX4(r0, r1, r2, r3, addr) \
    asm volatile("ldmatrix.sync.aligned.m8n8.x4.shared.b16 {%0,%1,%2,%3}, [%4];" \
        : "=r"(r0), "=r"(r1), "=r"(r2), "=r"(r3) : "r"(addr))
#define MMA16816(acc, af, b0, b1) \
    asm volatile("mma.sync.aligned.m16n8k16.row.col.f32.f16.f16.f32 " \
        "{%0,%1,%2,%3}, {%4,%5,%6,%7}, {%8,%9}, {%0,%1,%2,%3};" \
        : "+f"((acc)[0]), "+f"((acc)[1]), "+f"((acc)[2]), "+f"((acc)[3]) \
        : "r"((af)[0]), "r"((af)[1]), "r"((af)[2]), "r"((af)[3]), "r"(b0), "r"(b1))

// ---------------------------------------------------------------------------
// Single-product fp16 GEMM mainloop (NF=4): C[128,128] NT, fp32 accum.
// 8 warps 2(M) x 4(N); warp tile 64 x 32.  BK=32.  3-stage cp.async
// pipeline, prefetch depth 2.  Sized for 2 CTAs/SM (acc=64 regs).
// Stage layout (bytes): sA [128][40]h @0 (10240), sB [128][40]h @10240.
// STAGE = 20480.
// ---------------------------------------------------------------------------
__device__ __forceinline__ void mma_gemm1(
    const __half* __restrict__ A, const __half* __restrict__ B,
    int ldA, int ldB, int ksteps, float acc[4][4][4], char* sm)
{
    constexpr int STAGE = 20480;

    int t = threadIdx.x;
    int lane = t & 31, wid = t >> 5;
    int wm = wid & 1, wn = wid >> 1;

    #pragma unroll
    for (int mf = 0; mf < 4; mf++)
        #pragma unroll
        for (int nf = 0; nf < 4; nf++)
            #pragma unroll
            for (int e = 0; e < 4; e++) acc[mf][nf][e] = 0.f;

    auto load_tile = [&](int kc, int stg) {
        size_t kbase = (size_t)kc * 32;
        char* base = sm + stg * STAGE;
        {   // A: 128 rows x 4 quads = 512 positions, 2 per thread
            int row = t >> 2, q = t & 3;
            CP_ASYNC16(smem_u32(base + row * 80 + q * 16),
                       A + (size_t)row * ldA + kbase + q * 8);
            int idx2 = t + 256;
            int row2 = idx2 >> 2, q2 = idx2 & 3;
            CP_ASYNC16(smem_u32(base + row2 * 80 + q2 * 16),
                       A + (size_t)row2 * ldA + kbase + q2 * 8);
        }
        #pragma unroll
        for (int i = 0; i < 2; i++) {        // B: 128 rows x 4 quads
            int idx = t + (i << 8);
            int row = idx >> 2, q = idx & 3;
            CP_ASYNC16(smem_u32(base + 10240 + row * 80 + q * 16),
                       B + (size_t)row * ldB + kbase + q * 8);
        }
        CP_COMMIT();
    };

    load_tile(0, 0);
    if (ksteps > 1) load_tile(1, 1);

    int stg = 0;
    for (int c = 0; c < ksteps; c++) {
        if (c + 1 < ksteps) { CP_WAIT1(); }
        else                { CP_WAIT0(); }
        __syncthreads();
        if (c + 2 < ksteps) {
            int ns = stg + 2; if (ns >= 3) ns -= 3;
            load_tile(c + 2, ns);
        }

        char* base = sm + stg * STAGE;
        #pragma unroll
        for (int k16 = 0; k16 < 2; k16++) {
            uint32_t af[4][4];
            #pragma unroll
            for (int mf = 0; mf < 4; mf++) {
                int row = wm * 64 + mf * 16 + (lane & 15);
                int ko  = k16 * 16 + (lane >> 4) * 8;
                LDMX4(af[mf][0], af[mf][1], af[mf][2], af[mf][3],
                      smem_u32(base + row * 80 + ko * 2));
            }
            uint32_t bf[4][2];
            #pragma unroll
            for (int p = 0; p < 2; p++) {
                int nrow = wn * 32 + p * 16 + (lane & 7) + ((lane >> 4) << 3);
                int ko   = k16 * 16 + ((lane >> 3) & 1) * 8;
                uint32_t r0, r1, r2, r3;
                LDMX4(r0, r1, r2, r3, smem_u32(base + 10240 + nrow * 80 + ko * 2));
                bf[2*p][0] = r0; bf[2*p][1] = r1;
                bf[2*p+1][0] = r2; bf[2*p+1][1] = r3;
            }
            #pragma unroll
            for (int mf = 0; mf < 4; mf++)
                #pragma unroll
                for (int nf = 0; nf < 4; nf++)
                    MMA16816(acc[mf][nf], af[mf], bf[nf][0], bf[nf][1]);
        }
        stg++; if (stg >= 3) stg = 0;
        __syncthreads();
    }
}

#define SMEM_G (3 * 20480)   // 61440

// ---------------------------------------------------------------------------
// Kernel: fused fp32 -> fp16 convert for all 5 inputs.  grid 4096, block 256
// ---------------------------------------------------------------------------
__global__ __launch_bounds__(256) void cvt_all(
    const float* __restrict__ x,  const float* __restrict__ Wq,
    const float* __restrict__ Wk, const float* __restrict__ Wv,
    const float* __restrict__ Wp)
{
    int blk = blockIdx.x;
    const float* src;
    __half* dst;
    int local;
    if (blk < 2048)      { src = x;  dst = g_Xh;  local = blk; }
    else if (blk < 2560) { src = Wq; dst = g_Wqh; local = blk - 2048; }
    else if (blk < 3072) { src = Wk; dst = g_Wkh; local = blk - 2560; }
    else if (blk < 3584) { src = Wv; dst = g_Wvh; local = blk - 3072; }
    else                 { src = Wp; dst = g_Wph; local = blk - 3584; }
    int i = local * 256 + threadIdx.x;
    float4 v = *(const float4*)(src + 4 * (size_t)i);
    *(uint2*)((char*)dst + 8 * (size_t)i) = make_uint2(pack2h(v.x, v.y), pack2h(v.z, v.w));
}

// ---------------------------------------------------------------------------
// Kernel: QKV projection.  grid (8, 2, 192): z = qkv*64 + b*8 + h
// Q pre-scaled by 2^-4 (exact).
// ---------------------------------------------------------------------------
__global__ __launch_bounds__(256, 2) void qkv_g(
    const float* __restrict__ bq, const float* __restrict__ bk, const float* __restrict__ bv)
{
    extern __shared__ char sm[];
    int z = blockIdx.z, qkv = z >> 6, bh = z & 63, b = bh >> 3, h = bh & 7;
    int m0 = blockIdx.x * 128, n0 = blockIdx.y * 128;

    const __half* Wh = (qkv == 0) ? g_Wqh : (qkv == 1) ? g_Wkh : g_Wvh;
    const float* bias = ((qkv == 0) ? bq : (qkv == 1) ? bk : bv) + h * ND + n0;

    float acc[4][4][4];
    mma_gemm1(g_Xh + ((size_t)b * NS + m0) * ND,
              Wh + (size_t)h * ND * ND + (size_t)n0 * ND, ND, ND, 8, acc, sm);

    __half* Oh = (qkv == 0) ? g_Qh : (qkv == 1) ? g_Kh : g_Vh;
    float scale = (qkv == 0) ? 0.0625f : 1.0f;

    int lane = threadIdx.x & 31, wid = threadIdx.x >> 5;
    int wm = wid & 1, wn = wid >> 1;
    #pragma unroll
    for (int mf = 0; mf < 4; mf++) {
        int r = m0 + wm * 64 + mf * 16 + (lane >> 2);
        #pragma unroll
        for (int nf = 0; nf < 4; nf++) {
            int cc = wn * 32 + nf * 8 + ((lane & 3) << 1);
            float2 bb = *(const float2*)(bias + cc);
            size_t base0 = ((size_t)bh * NS + r) * ND + n0 + cc;
            size_t base1 = base0 + 8 * ND;
            *(uint32_t*)(Oh + base0) = pack2h((acc[mf][nf][0] + bb.x) * scale,
                                              (acc[mf][nf][1] + bb.y) * scale);
            *(uint32_t*)(Oh + base1) = pack2h((acc[mf][nf][2] + bb.x) * scale,
                                              (acc[mf][nf][3] + bb.y) * scale);
        }
    }
}

// ---------------------------------------------------------------------------
// Kernel: V transpose [bh,t,e] -> [bh,e,t]. grid (32, 8, 64), block (32,8)
// ---------------------------------------------------------------------------
__global__ void vt_kernel()
{
    __shared__ __half th[32][33];
    int bh = blockIdx.z, t0 = blockIdx.x * 32, e0 = blockIdx.y * 32;
    int tx = threadIdx.x, ty = threadIdx.y;
    #pragma unroll
    for (int j = 0; j < 4; j++) {
        int rr = ty + j * 8;
        th[rr][tx] = g_Vh[((size_t)bh * NS + t0 + rr) * ND + e0 + tx];
    }
    __syncthreads();
    #pragma unroll
    for (int j = 0; j < 4; j++) {
        int er = ty + j * 8;
        g_Vth[((size_t)bh * ND + e0 + er) * NS + t0 + tx] = th[tx][er];
    }
}

// ---------------------------------------------------------------------------
// Kernel: scores = (Q/16) K^T -> fp16 logits.  grid (8, 8, 64)
// ---------------------------------------------------------------------------
__global__ __launch_bounds__(256, 2) void scores_g()
{
    extern __shared__ char sm[];
    int bh = blockIdx.z, m0 = blockIdx.x * 128, n0 = blockIdx.y * 128;
    float acc[4][4][4];
    mma_gemm1(g_Qh + ((size_t)bh * NS + m0) * ND,
              g_Kh + ((size_t)bh * NS + n0) * ND, ND, ND, 8, acc, sm);

    int lane = threadIdx.x & 31, wid = threadIdx.x >> 5;
    int wm = wid & 1, wn = wid >> 1;
    #pragma unroll
    for (int mf = 0; mf < 4; mf++) {
        int r = m0 + wm * 64 + mf * 16 + (lane >> 2);
        #pragma unroll
        for (int nf = 0; nf < 4; nf++) {
            int cc = n0 + wn * 32 + nf * 8 + ((lane & 3) << 1);
            __half* d0 = g_Ph + ((size_t)bh * NS + r) * NS + cc;
            *(uint32_t*)d0 = pack2h(acc[mf][nf][0], acc[mf][nf][1]);
            *(uint32_t*)(d0 + 8 * NS) = pack2h(acc[mf][nf][2], acc[mf][nf][3]);
        }
    }
}

// ---------------------------------------------------------------------------
// Kernel: in-place softmax over keys on fp16 logits.  grid 65536, block 256
// ---------------------------------------------------------------------------
__global__ __launch_bounds__(256) void softmax_kernel()
{
    size_t rowoff = (size_t)blockIdx.x * NS;
    int t = threadIdx.x;
    uint2 raw = *(uint2*)((char*)g_Ph + 2 * (rowoff + (t << 2)));
    __half2 h01 = *(__half2*)&raw.x, h23 = *(__half2*)&raw.y;
    float2 f01 = __half22float2(h01), f23 = __half22float2(h23);
    float4 v = make_float4(f01.x, f01.y, f23.x, f23.y);
    __shared__ float smx[8], ssm[8];

    float m = fmaxf(fmaxf(v.x, v.y), fmaxf(v.z, v.w));
    #pragma unroll
    for (int o = 16; o > 0; o >>= 1) m = fmaxf(m, __shfl_xor_sync(0xffffffffu, m, o));
    if ((t & 31) == 0) smx[t >> 5] = m;
    __syncthreads();
    if (t < 32) {
        float mm = (t < 8) ? smx[t] : -3.0e38f;
        #pragma unroll
        for (int o = 4; o > 0; o >>= 1) mm = fmaxf(mm, __shfl_xor_sync(0xffffffffu, mm, o));
        if (t == 0) smx[0] = mm;
    }
    __syncthreads();
    m = smx[0];
    v.x = __expf(v.x - m); v.y = __expf(v.y - m);
    v.z = __expf(v.z - m); v.w = __expf(v.w - m);
    float s = v.x + v.y + v.z + v.w;
    #pragma unroll
    for (int o = 16; o > 0; o >>= 1) s += __shfl_xor_sync(0xffffffffu, s, o);
    if ((t & 31) == 0) ssm[t >> 5] = s;
    __syncthreads();
    if (t < 32) {
        float sv = (t < 8) ? ssm[t] : 0.f;
        #pragma unroll
        for (int o = 4; o > 0; o >>= 1) sv += __shfl_xor_sync(0xffffffffu, sv, o);
        if (t == 0) ssm[0] = sv;
    }
    __syncthreads();
    float inv = 1.0f / ssm[0];

    *(uint2*)((char*)g_Ph + 2 * (rowoff + (t << 2))) =
        make_uint2(pack2h(v.x * inv, v.y * inv), pack2h(v.z * inv, v.w * inv));
}

// ---------------------------------------------------------------------------
// Kernel: O = P @ V (B = V^T).  grid (8, 2, 64) -> concat layout
// ---------------------------------------------------------------------------
__global__ __launch_bounds__(256, 2) void pv_g()
{
    extern __shared__ char sm[];
    int bh = blockIdx.z, b = bh >> 3, h = bh & 7;
    int m0 = blockIdx.x * 128, n0 = blockIdx.y * 128;
    float acc[4][4][4];
    mma_gemm1(g_Ph + ((size_t)bh * NS + m0) * NS,
              g_Vth + (size_t)bh * ND * NS + (size_t)n0 * NS, NS, NS, 32, acc, sm);

    int lane = threadIdx.x & 31, wid = threadIdx.x >> 5;
    int wm = wid & 1, wn = wid >> 1;
    #pragma unroll
    for (int mf = 0; mf < 4; mf++) {
        int r = m0 + wm * 64 + mf * 16 + (lane >> 2);
        #pragma unroll
        for (int nf = 0; nf < 4; nf++) {
            int cc = n0 + wn * 32 + nf * 8 + ((lane & 3) << 1);
            size_t base0 = ((size_t)(b * NS + r)) * HD + h * ND + cc;
            size_t base1 = base0 + 8 * HD;
            *(uint32_t*)(g_Oh + base0) = pack2h(acc[mf][nf][0], acc[mf][nf][1]);
            *(uint32_t*)(g_Oh + base1) = pack2h(acc[mf][nf][2], acc[mf][nf][3]);
        }
    }
}

// ---------------------------------------------------------------------------
// Kernel: out = concat(O) @ Wp^T.  grid (64, 2, 1)
// ---------------------------------------------------------------------------
__global__ __launch_bounds__(256, 2) void proj_g(float* __restrict__ out)
{
    extern __shared__ char sm[];
    int m0 = blockIdx.x * 128, n0 = blockIdx.y * 128;
    float acc[4][4][4];
    mma_gemm1(g_Oh + (size_t)m0 * HD, g_Wph + (size_t)n0 * HD,
              HD, HD, 64, acc, sm);

    int lane = threadIdx.x & 31, wid = threadIdx.x >> 5;
    int wm = wid & 1, wn = wid >> 1;
    #pragma unroll
    for (int mf = 0; mf < 4; mf++) {
        int r = m0 + wm * 64 + mf * 16 + (lane >> 2);
        #pragma unroll
        for (int nf = 0; nf < 4; nf++) {
            int cc = n0 + wn * 32 + nf * 8 + ((lane & 3) << 1);
            float* d0 = out + (size_t)r * ND + cc;
            *(float2*)d0 = make_float2(acc[mf][nf][0], acc[mf][nf][1]);
            *(float2*)(d0 + 8 * ND) = make_float2(acc[mf][nf][2], acc[mf][nf][3]);
        }
    }
}

// ---------------------------------------------------------------------------
extern "C" void kernel_launch(void* const* d_in, const int* in_sizes, int n_in,
                              void* d_out, int out_size)
{
    const float* x  = (const float*)d_in[0];
    const float* Wq = (const float*)d_in[1];
    const float* Wk = (const float*)d_in[2];
    const float* Wv = (const float*)d_in[3];
    const float* bq = (const float*)d_in[4];
    const float* bk = (const float*)d_in[5];
    const float* bv = (const float*)d_in[6];
    const float* Wp = (const float*)d_in[7];
    float* out = (float*)d_out;

    cudaFuncSetAttribute(qkv_g,    cudaFuncAttributeMaxDynamicSharedMemorySize, SMEM_G);
    cudaFuncSetAttribute(scores_g, cudaFuncAttributeMaxDynamicSharedMemorySize, SMEM_G);
    cudaFuncSetAttribute(pv_g,     cudaFuncAttributeMaxDynamicSharedMemorySize, SMEM_G);
    cudaFuncSetAttribute(proj_g,   cudaFuncAttributeMaxDynamicSharedMemorySize, SMEM_G);

    cvt_all<<<4096, 256>>>(x, Wq, Wk, Wv, Wp);

    dim3 gq(8, 2, 192);
    qkv_g<<<gq, 256, SMEM_G>>>(bq, bk, bv);

    dim3 gt(32, 8, 64);
    vt_kernel<<<gt, dim3(32, 8)>>>();

    dim3 gs(8, 8, 64);
    scores_g<<<gs, 256, SMEM_G>>>();

    softmax_kernel<<<65536, 256>>>();

    dim3 gp(8, 2, 64);
    pv_g<<<gp, 256, SMEM_G>>>();

    dim3 go(64, 2, 1);
    proj_g<<<go, 256, SMEM_G>>>(out);
}

// round 14
// speedup vs baseline: 3.8519x; 1.1365x over previous
#include <cuda_runtime.h>
#include <cuda_fp16.h>
#include <cstdint>

#define NS 1024
#define ND 256
#define NH 8
#define HD 2048

// ---------------- scratch (static device memory; no allocs) ----------------
__device__ __half g_Xh[2097152];
__device__ __half g_Wqh[524288], g_Wkh[524288], g_Wvh[524288], g_Wph[524288];
__device__ __half g_Qh[16777216], g_Kh[16777216], g_Vh[16777216];
__device__ __half g_Vth[16777216];                                // V transposed [bh, e, t]
__device__ __half g_Ph[67108864];                                 // fp16 logits -> probs (in place)
__device__ __half g_Oh[16777216];                                 // [B*S, H*D] concat layout

// ---------------- helpers ----------------
__device__ __forceinline__ uint32_t smem_u32(const void* p) {
    uint32_t a;
    asm("{ .reg .u64 t; cvta.to.shared.u64 t, %1; cvt.u32.u64 %0, t; }" : "=r"(a) : "l"(p));
    return a;
}

__device__ __forceinline__ uint32_t pack2h(float a, float b) {
    __half h0 = __float2half_rn(a), h1 = __float2half_rn(b);
    return (uint32_t)__half_as_ushort(h0) | ((uint32_t)__half_as_ushort(h1) << 16);
}

#define CP_ASYNC16(saddr, gptr) \
    asm volatile("cp.async.cg.shared.global [%0], [%1], 16;" :: "r"(saddr), "l"(gptr))
#define CP_COMMIT() asm volatile("cp.async.commit_group;")
#define CP_WAIT1()  asm volatile("cp.async.wait_group 1;")
#define CP_WAIT0()  asm volatile("cp.async.wait_group 0;")
#define LDMX4(r0, r1, r2, r3, addr) \
    asm volatile("ldmatrix.sync.aligned.m8n8.x4.shared.b16 {%0,%1,%2,%3}, [%4];" \
        : "=r"(r0), "=r"(r1), "=r"(r2), "=r"(r3) : "r"(addr))
#define MMA16816(acc, af, b0, b1) \
    asm volatile("mma.sync.aligned.m16n8k16.row.col.f32.f16.f16.f32 " \
        "{%0,%1,%2,%3}, {%4,%5,%6,%7}, {%8,%9}, {%0,%1,%2,%3};" \
        : "+f"((acc)[0]), "+f"((acc)[1]), "+f"((acc)[2]), "+f"((acc)[3]) \
        : "r"((af)[0]), "r"((af)[1]), "r"((af)[2]), "r"((af)[3]), "r"(b0), "r"(b1))

// ---------------------------------------------------------------------------
// Single-product fp16 GEMM mainloop (NF=4): C[128,128] NT, fp32 accum.
// 8 warps 2(M) x 4(N); warp tile 64 x 32.  BK=32.  3-stage cp.async ring
// with REGISTER POINTER ROTATION (no dynamic stage indexing), precomputed
// ldmatrix/cp.async offsets, advancing global pointers, ONE barrier/chunk.
// Stage layout (bytes): sA [128][40]h @0 (10240), sB [128][40]h @10240.
// STAGE = 20480.  Sized for 2 CTAs/SM (acc = 64 regs).
// ---------------------------------------------------------------------------
__device__ __forceinline__ void mma_gemm1(
    const __half* __restrict__ A, const __half* __restrict__ B,
    int ldA, int ldB, int ksteps, float acc[4][4][4], char* sm)
{
    constexpr int STAGE = 20480;

    int t = threadIdx.x;
    int lane = t & 31, wid = t >> 5;
    int wm = wid & 1, wn = wid >> 1;

    #pragma unroll
    for (int mf = 0; mf < 4; mf++)
        #pragma unroll
        for (int nf = 0; nf < 4; nf++)
            #pragma unroll
            for (int e = 0; e < 4; e++) acc[mf][nf][e] = 0.f;

    uint32_t sb = smem_u32(sm);

    // per-thread cp.async store offsets (relative to stage base)
    int r1 = t >> 2,          q1 = t & 3;
    int r2 = (t + 256) >> 2,  q2 = (t + 256) & 3;
    uint32_t stA1 = (uint32_t)(r1 * 80 + q1 * 16);
    uint32_t stA2 = (uint32_t)(r2 * 80 + q2 * 16);
    uint32_t stB1 = 10240 + stA1;
    uint32_t stB2 = 10240 + stA2;

    // advancing global pointers (one add per prefetch, no kc*32 IMADs)
    const __half* gA1 = A + (size_t)r1 * ldA + q1 * 8;
    const __half* gA2 = A + (size_t)r2 * ldA + q2 * 8;
    const __half* gB1 = B + (size_t)r1 * ldB + q1 * 8;
    const __half* gB2 = B + (size_t)r2 * ldB + q2 * 8;

    // per-warp ldmatrix offsets (relative to stage base)
    uint32_t aoff[2][4], boff[2][2];
    #pragma unroll
    for (int k16 = 0; k16 < 2; k16++) {
        #pragma unroll
        for (int mf = 0; mf < 4; mf++) {
            int row = wm * 64 + mf * 16 + (lane & 15);
            int ko  = k16 * 16 + (lane >> 4) * 8;
            aoff[k16][mf] = (uint32_t)(row * 80 + ko * 2);
        }
        #pragma unroll
        for (int p = 0; p < 2; p++) {
            int nrow = wn * 32 + p * 16 + (lane & 7) + ((lane >> 4) << 3);
            int ko   = k16 * 16 + ((lane >> 3) & 1) * 8;
            boff[k16][p] = (uint32_t)(10240 + nrow * 80 + ko * 2);
        }
    }

    auto load_tile = [&](uint32_t base) {
        CP_ASYNC16(base + stA1, gA1);
        CP_ASYNC16(base + stA2, gA2);
        CP_ASYNC16(base + stB1, gB1);
        CP_ASYNC16(base + stB2, gB2);
        CP_COMMIT();
        gA1 += 32; gA2 += 32; gB1 += 32; gB2 += 32;
    };

    uint32_t s0 = sb, s1 = sb + STAGE, s2 = sb + 2 * STAGE;
    load_tile(s0);
    if (ksteps > 1) load_tile(s1);

    for (int c = 0; c < ksteps; c++) {
        if (c + 1 < ksteps) { CP_WAIT1(); }
        else                { CP_WAIT0(); }
        __syncthreads();                  // orders compute(c-1) before prefetch into s2
        if (c + 2 < ksteps) load_tile(s2);

        #pragma unroll
        for (int k16 = 0; k16 < 2; k16++) {
            uint32_t af[4][4];
            #pragma unroll
            for (int mf = 0; mf < 4; mf++)
                LDMX4(af[mf][0], af[mf][1], af[mf][2], af[mf][3], s0 + aoff[k16][mf]);
            uint32_t bf[4][2];
            #pragma unroll
            for (int p = 0; p < 2; p++) {
                uint32_t rr0, rr1, rr2, rr3;
                LDMX4(rr0, rr1, rr2, rr3, s0 + boff[k16][p]);
                bf[2*p][0] = rr0; bf[2*p][1] = rr1;
                bf[2*p+1][0] = rr2; bf[2*p+1][1] = rr3;
            }
            #pragma unroll
            for (int mf = 0; mf < 4; mf++)
                #pragma unroll
                for (int nf = 0; nf < 4; nf++)
                    MMA16816(acc[mf][nf], af[mf], bf[nf][0], bf[nf][1]);
        }
        uint32_t tmp = s0; s0 = s1; s1 = s2; s2 = tmp;   // rotate ring
    }
}

#define SMEM_G (3 * 20480)   // 61440

// ---------------------------------------------------------------------------
// Kernel: fused fp32 -> fp16 convert for all 5 inputs.  grid 4096, block 256
// ---------------------------------------------------------------------------
__global__ __launch_bounds__(256) void cvt_all(
    const float* __restrict__ x,  const float* __restrict__ Wq,
    const float* __restrict__ Wk, const float* __restrict__ Wv,
    const float* __restrict__ Wp)
{
    int blk = blockIdx.x;
    const float* src;
    __half* dst;
    int local;
    if (blk < 2048)      { src = x;  dst = g_Xh;  local = blk; }
    else if (blk < 2560) { src = Wq; dst = g_Wqh; local = blk - 2048; }
    else if (blk < 3072) { src = Wk; dst = g_Wkh; local = blk - 2560; }
    else if (blk < 3584) { src = Wv; dst = g_Wvh; local = blk - 3072; }
    else                 { src = Wp; dst = g_Wph; local = blk - 3584; }
    int i = local * 256 + threadIdx.x;
    float4 v = *(const float4*)(src + 4 * (size_t)i);
    *(uint2*)((char*)dst + 8 * (size_t)i) = make_uint2(pack2h(v.x, v.y), pack2h(v.z, v.w));
}

// ---------------------------------------------------------------------------
// Kernel: QKV projection.  grid (8, 2, 192): z = qkv*64 + b*8 + h
// Q pre-scaled by 2^-4 (exact).
// ---------------------------------------------------------------------------
__global__ __launch_bounds__(256, 2) void qkv_g(
    const float* __restrict__ bq, const float* __restrict__ bk, const float* __restrict__ bv)
{
    extern __shared__ char sm[];
    int z = blockIdx.z, qkv = z >> 6, bh = z & 63, b = bh >> 3, h = bh & 7;
    int m0 = blockIdx.x * 128, n0 = blockIdx.y * 128;

    const __half* Wh = (qkv == 0) ? g_Wqh : (qkv == 1) ? g_Wkh : g_Wvh;
    const float* bias = ((qkv == 0) ? bq : (qkv == 1) ? bk : bv) + h * ND + n0;

    float acc[4][4][4];
    mma_gemm1(g_Xh + ((size_t)b * NS + m0) * ND,
              Wh + (size_t)h * ND * ND + (size_t)n0 * ND, ND, ND, 8, acc, sm);

    __half* Oh = (qkv == 0) ? g_Qh : (qkv == 1) ? g_Kh : g_Vh;
    float scale = (qkv == 0) ? 0.0625f : 1.0f;

    int lane = threadIdx.x & 31, wid = threadIdx.x >> 5;
    int wm = wid & 1, wn = wid >> 1;
    #pragma unroll
    for (int mf = 0; mf < 4; mf++) {
        int r = m0 + wm * 64 + mf * 16 + (lane >> 2);
        #pragma unroll
        for (int nf = 0; nf < 4; nf++) {
            int cc = wn * 32 + nf * 8 + ((lane & 3) << 1);
            float2 bb = *(const float2*)(bias + cc);
            size_t base0 = ((size_t)bh * NS + r) * ND + n0 + cc;
            size_t base1 = base0 + 8 * ND;
            *(uint32_t*)(Oh + base0) = pack2h((acc[mf][nf][0] + bb.x) * scale,
                                              (acc[mf][nf][1] + bb.y) * scale);
            *(uint32_t*)(Oh + base1) = pack2h((acc[mf][nf][2] + bb.x) * scale,
                                              (acc[mf][nf][3] + bb.y) * scale);
        }
    }
}

// ---------------------------------------------------------------------------
// Kernel: V transpose [bh,t,e] -> [bh,e,t]. grid (32, 8, 64), block (32,8)
// ---------------------------------------------------------------------------
__global__ void vt_kernel()
{
    __shared__ __half th[32][33];
    int bh = blockIdx.z, t0 = blockIdx.x * 32, e0 = blockIdx.y * 32;
    int tx = threadIdx.x, ty = threadIdx.y;
    #pragma unroll
    for (int j = 0; j < 4; j++) {
        int rr = ty + j * 8;
        th[rr][tx] = g_Vh[((size_t)bh * NS + t0 + rr) * ND + e0 + tx];
    }
    __syncthreads();
    #pragma unroll
    for (int j = 0; j < 4; j++) {
        int er = ty + j * 8;
        g_Vth[((size_t)bh * ND + e0 + er) * NS + t0 + tx] = th[tx][er];
    }
}

// ---------------------------------------------------------------------------
// Kernel: scores = (Q/16) K^T -> fp16 logits.  grid (8, 8, 64)
// ---------------------------------------------------------------------------
__global__ __launch_bounds__(256, 2) void scores_g()
{
    extern __shared__ char sm[];
    int bh = blockIdx.z, m0 = blockIdx.x * 128, n0 = blockIdx.y * 128;
    float acc[4][4][4];
    mma_gemm1(g_Qh + ((size_t)bh * NS + m0) * ND,
              g_Kh + ((size_t)bh * NS + n0) * ND, ND, ND, 8, acc, sm);

    int lane = threadIdx.x & 31, wid = threadIdx.x >> 5;
    int wm = wid & 1, wn = wid >> 1;
    #pragma unroll
    for (int mf = 0; mf < 4; mf++) {
        int r = m0 + wm * 64 + mf * 16 + (lane >> 2);
        #pragma unroll
        for (int nf = 0; nf < 4; nf++) {
            int cc = n0 + wn * 32 + nf * 8 + ((lane & 3) << 1);
            __half* d0 = g_Ph + ((size_t)bh * NS + r) * NS + cc;
            *(uint32_t*)d0 = pack2h(acc[mf][nf][0], acc[mf][nf][1]);
            *(uint32_t*)(d0 + 8 * NS) = pack2h(acc[mf][nf][2], acc[mf][nf][3]);
        }
    }
}

// ---------------------------------------------------------------------------
// Kernel: in-place softmax over keys on fp16 logits.  grid 65536, block 256
// ---------------------------------------------------------------------------
__global__ __launch_bounds__(256) void softmax_kernel()
{
    size_t rowoff = (size_t)blockIdx.x * NS;
    int t = threadIdx.x;
    uint2 raw = *(uint2*)((char*)g_Ph + 2 * (rowoff + (t << 2)));
    __half2 h01 = *(__half2*)&raw.x, h23 = *(__half2*)&raw.y;
    float2 f01 = __half22float2(h01), f23 = __half22float2(h23);
    float4 v = make_float4(f01.x, f01.y, f23.x, f23.y);
    __shared__ float smx[8], ssm[8];

    float m = fmaxf(fmaxf(v.x, v.y), fmaxf(v.z, v.w));
    #pragma unroll
    for (int o = 16; o > 0; o >>= 1) m = fmaxf(m, __shfl_xor_sync(0xffffffffu, m, o));
    if ((t & 31) == 0) smx[t >> 5] = m;
    __syncthreads();
    if (t < 32) {
        float mm = (t < 8) ? smx[t] : -3.0e38f;
        #pragma unroll
        for (int o = 4; o > 0; o >>= 1) mm = fmaxf(mm, __shfl_xor_sync(0xffffffffu, mm, o));
        if (t == 0) smx[0] = mm;
    }
    __syncthreads();
    m = smx[0];
    v.x = __expf(v.x - m); v.y = __expf(v.y - m);
    v.z = __expf(v.z - m); v.w = __expf(v.w - m);
    float s = v.x + v.y + v.z + v.w;
    #pragma unroll
    for (int o = 16; o > 0; o >>= 1) s += __shfl_xor_sync(0xffffffffu, s, o);
    if ((t & 31) == 0) ssm[t >> 5] = s;
    __syncthreads();
    if (t < 32) {
        float sv = (t < 8) ? ssm[t] : 0.f;
        #pragma unroll
        for (int o = 4; o > 0; o >>= 1) sv += __shfl_xor_sync(0xffffffffu, sv, o);
        if (t == 0) ssm[0] = sv;
    }
    __syncthreads();
    float inv = 1.0f / ssm[0];

    *(uint2*)((char*)g_Ph + 2 * (rowoff + (t << 2))) =
        make_uint2(pack2h(v.x * inv, v.y * inv), pack2h(v.z * inv, v.w * inv));
}

// ---------------------------------------------------------------------------
// Kernel: O = P @ V (B = V^T).  grid (8, 2, 64) -> concat layout
// ---------------------------------------------------------------------------
__global__ __launch_bounds__(256, 2) void pv_g()
{
    extern __shared__ char sm[];
    int bh = blockIdx.z, b = bh >> 3, h = bh & 7;
    int m0 = blockIdx.x * 128, n0 = blockIdx.y * 128;
    float acc[4][4][4];
    mma_gemm1(g_Ph + ((size_t)bh * NS + m0) * NS,
              g_Vth + (size_t)bh * ND * NS + (size_t)n0 * NS, NS, NS, 32, acc, sm);

    int lane = threadIdx.x & 31, wid = threadIdx.x >> 5;
    int wm = wid & 1, wn = wid >> 1;
    #pragma unroll
    for (int mf = 0; mf < 4; mf++) {
        int r = m0 + wm * 64 + mf * 16 + (lane >> 2);
        #pragma unroll
        for (int nf = 0; nf < 4; nf++) {
            int cc = n0 + wn * 32 + nf * 8 + ((lane & 3) << 1);
            size_t base0 = ((size_t)(b * NS + r)) * HD + h * ND + cc;
            size_t base1 = base0 + 8 * HD;
            *(uint32_t*)(g_Oh + base0) = pack2h(acc[mf][nf][0], acc[mf][nf][1]);
            *(uint32_t*)(g_Oh + base1) = pack2h(acc[mf][nf][2], acc[mf][nf][3]);
        }
    }
}

// ---------------------------------------------------------------------------
// Kernel: out = concat(O) @ Wp^T.  grid (64, 2, 1)
// ---------------------------------------------------------------------------
__global__ __launch_bounds__(256, 2) void proj_g(float* __restrict__ out)
{
    extern __shared__ char sm[];
    int m0 = blockIdx.x * 128, n0 = blockIdx.y * 128;
    float acc[4][4][4];
    mma_gemm1(g_Oh + (size_t)m0 * HD, g_Wph + (size_t)n0 * HD,
              HD, HD, 64, acc, sm);

    int lane = threadIdx.x & 31, wid = threadIdx.x >> 5;
    int wm = wid & 1, wn = wid >> 1;
    #pragma unroll
    for (int mf = 0; mf < 4; mf++) {
        int r = m0 + wm * 64 + mf * 16 + (lane >> 2);
        #pragma unroll
        for (int nf = 0; nf < 4; nf++) {
            int cc = n0 + wn * 32 + nf * 8 + ((lane & 3) << 1);
            float* d0 = out + (size_t)r * ND + cc;
            *(float2*)d0 = make_float2(acc[mf][nf][0], acc[mf][nf][1]);
            *(float2*)(d0 + 8 * ND) = make_float2(acc[mf][nf][2], acc[mf][nf][3]);
        }
    }
}

// ---------------------------------------------------------------------------
extern "C" void kernel_launch(void* const* d_in, const int* in_sizes, int n_in,
                              void* d_out, int out_size)
{
    const float* x  = (const float*)d_in[0];
    const float* Wq = (const float*)d_in[1];
    const float* Wk = (const float*)d_in[2];
    const float* Wv = (const float*)d_in[3];
    const float* bq = (const float*)d_in[4];
    const float* bk = (const float*)d_in[5];
    const float* bv = (const float*)d_in[6];
    const float* Wp = (const float*)d_in[7];
    float* out = (float*)d_out;

    cudaFuncSetAttribute(qkv_g,    cudaFuncAttributeMaxDynamicSharedMemorySize, SMEM_G);
    cudaFuncSetAttribute(scores_g, cudaFuncAttributeMaxDynamicSharedMemorySize, SMEM_G);
    cudaFuncSetAttribute(pv_g,     cudaFuncAttributeMaxDynamicSharedMemorySize, SMEM_G);
    cudaFuncSetAttribute(proj_g,   cudaFuncAttributeMaxDynamicSharedMemorySize, SMEM_G);

    cvt_all<<<4096, 256>>>(x, Wq, Wk, Wv, Wp);

    dim3 gq(8, 2, 192);
    qkv_g<<<gq, 256, SMEM_G>>>(bq, bk, bv);

    dim3 gt(32, 8, 64);
    vt_kernel<<<gt, dim3(32, 8)>>>();

    dim3 gs(8, 8, 64);
    scores_g<<<gs, 256, SMEM_G>>>();

    softmax_kernel<<<65536, 256>>>();

    dim3 gp(8, 2, 64);
    pv_g<<<gp, 256, SMEM_G>>>();

    dim3 go(64, 2, 1);
    proj_g<<<go, 256, SMEM_G>>>(out);
}

// round 15
// speedup vs baseline: 4.4164x; 1.1466x over previous
#include <cuda_runtime.h>
#include <cuda_fp16.h>
#include <cstdint>

#define NS 1024
#define ND 256
#define NH 8
#define HD 2048

// ---------------- scratch (static device memory; no allocs) ----------------
__device__ __half g_Xh[2097152];
__device__ __half g_Wqh[524288], g_Wkh[524288], g_Wvh[524288], g_Wph[524288];
__device__ __half g_Qh[16777216], g_Kh[16777216];
__device__ __half g_Vth[16777216];                                // V transposed [bh, e, t]
__device__ __half g_Ph[67108864];                                 // fp16 logits -> probs (in place)
__device__ __half g_Oh[16777216];                                 // [B*S, H*D] concat layout

// ---------------- helpers ----------------
__device__ __forceinline__ uint32_t smem_u32(const void* p) {
    uint32_t a;
    asm("{ .reg .u64 t; cvta.to.shared.u64 t, %1; cvt.u32.u64 %0, t; }" : "=r"(a) : "l"(p));
    return a;
}

__device__ __forceinline__ uint32_t pack2h(float a, float b) {
    __half h0 = __float2half_rn(a), h1 = __float2half_rn(b);
    return (uint32_t)__half_as_ushort(h0) | ((uint32_t)__half_as_ushort(h1) << 16);
}

#define CP_ASYNC16(saddr, gptr) \
    asm volatile("cp.async.cg.shared.global [%0], [%1], 16;" :: "r"(saddr), "l"(gptr))
#define CP_COMMIT() asm volatile("cp.async.commit_group;")
#define CP_WAIT1()  asm volatile("cp.async.wait_group 1;")
#define CP_WAIT0()  asm volatile("cp.async.wait_group 0;")
#define LDMX4(r0, r1, r2, r3, addr) \
    asm volatile("ldmatrix.sync.aligned.m8n8.x4.shared.b16 {%0,%1,%2,%3}, [%4];" \
        : "=r"(r0), "=r"(r1), "=r"(r2), "=r"(r3) : "r"(addr))
#define MMA16816(acc, af, b0, b1) \
    asm volatile("mma.sync.aligned.m16n8k16.row.col.f32.f16.f16.f32 " \
        "{%0,%1,%2,%3}, {%4,%5,%6,%7}, {%8,%9}, {%0,%1,%2,%3};" \
        : "+f"((acc)[0]), "+f"((acc)[1]), "+f"((acc)[2]), "+f"((acc)[3]) \
        : "r"((af)[0]), "r"((af)[1]), "r"((af)[2]), "r"((af)[3]), "r"(b0), "r"(b1))

// ---------------------------------------------------------------------------
// Single-product fp16 GEMM mainloop (NF=4): C[128,128] NT, fp32 accum.
// 8 warps 2(M) x 4(N); warp tile 64 x 32.  BK=32.  3-stage cp.async ring,
// register pointer rotation, precomputed offsets, one barrier per chunk.
// Stage layout (bytes): sA [128][40]h @0 (10240), sB [128][40]h @10240.
// STAGE = 20480.  Sized for 2 CTAs/SM (acc = 64 regs).
// ---------------------------------------------------------------------------
__device__ __forceinline__ void mma_gemm1(
    const __half* __restrict__ A, const __half* __restrict__ B,
    int ldA, int ldB, int ksteps, float acc[4][4][4], char* sm)
{
    constexpr int STAGE = 20480;

    int t = threadIdx.x;
    int lane = t & 31, wid = t >> 5;
    int wm = wid & 1, wn = wid >> 1;

    #pragma unroll
    for (int mf = 0; mf < 4; mf++)
        #pragma unroll
        for (int nf = 0; nf < 4; nf++)
            #pragma unroll
            for (int e = 0; e < 4; e++) acc[mf][nf][e] = 0.f;

    uint32_t sb = smem_u32(sm);

    int r1 = t >> 2,          q1 = t & 3;
    int r2 = (t + 256) >> 2,  q2 = (t + 256) & 3;
    uint32_t stA1 = (uint32_t)(r1 * 80 + q1 * 16);
    uint32_t stA2 = (uint32_t)(r2 * 80 + q2 * 16);
    uint32_t stB1 = 10240 + stA1;
    uint32_t stB2 = 10240 + stA2;

    const __half* gA1 = A + (size_t)r1 * ldA + q1 * 8;
    const __half* gA2 = A + (size_t)r2 * ldA + q2 * 8;
    const __half* gB1 = B + (size_t)r1 * ldB + q1 * 8;
    const __half* gB2 = B + (size_t)r2 * ldB + q2 * 8;

    uint32_t aoff[2][4], boff[2][2];
    #pragma unroll
    for (int k16 = 0; k16 < 2; k16++) {
        #pragma unroll
        for (int mf = 0; mf < 4; mf++) {
            int row = wm * 64 + mf * 16 + (lane & 15);
            int ko  = k16 * 16 + (lane >> 4) * 8;
            aoff[k16][mf] = (uint32_t)(row * 80 + ko * 2);
        }
        #pragma unroll
        for (int p = 0; p < 2; p++) {
            int nrow = wn * 32 + p * 16 + (lane & 7) + ((lane >> 4) << 3);
            int ko   = k16 * 16 + ((lane >> 3) & 1) * 8;
            boff[k16][p] = (uint32_t)(10240 + nrow * 80 + ko * 2);
        }
    }

    auto load_tile = [&](uint32_t base) {
        CP_ASYNC16(base + stA1, gA1);
        CP_ASYNC16(base + stA2, gA2);
        CP_ASYNC16(base + stB1, gB1);
        CP_ASYNC16(base + stB2, gB2);
        CP_COMMIT();
        gA1 += 32; gA2 += 32; gB1 += 32; gB2 += 32;
    };

    uint32_t s0 = sb, s1 = sb + STAGE, s2 = sb + 2 * STAGE;
    load_tile(s0);
    if (ksteps > 1) load_tile(s1);

    for (int c = 0; c < ksteps; c++) {
        if (c + 1 < ksteps) { CP_WAIT1(); }
        else                { CP_WAIT0(); }
        __syncthreads();
        if (c + 2 < ksteps) load_tile(s2);

        #pragma unroll
        for (int k16 = 0; k16 < 2; k16++) {
            uint32_t af[4][4];
            #pragma unroll
            for (int mf = 0; mf < 4; mf++)
                LDMX4(af[mf][0], af[mf][1], af[mf][2], af[mf][3], s0 + aoff[k16][mf]);
            uint32_t bf[4][2];
            #pragma unroll
            for (int p = 0; p < 2; p++) {
                uint32_t rr0, rr1, rr2, rr3;
                LDMX4(rr0, rr1, rr2, rr3, s0 + boff[k16][p]);
                bf[2*p][0] = rr0; bf[2*p][1] = rr1;
                bf[2*p+1][0] = rr2; bf[2*p+1][1] = rr3;
            }
            #pragma unroll
            for (int mf = 0; mf < 4; mf++)
                #pragma unroll
                for (int nf = 0; nf < 4; nf++)
                    MMA16816(acc[mf][nf], af[mf], bf[nf][0], bf[nf][1]);
        }
        uint32_t tmp = s0; s0 = s1; s1 = s2; s2 = tmp;
    }
}

#define SMEM_G (3 * 20480)   // 61440

// ---------------------------------------------------------------------------
// Kernel: fused fp32 -> fp16 convert for all 5 inputs.  grid 4096, block 256
// ---------------------------------------------------------------------------
__global__ __launch_bounds__(256) void cvt_all(
    const float* __restrict__ x,  const float* __restrict__ Wq,
    const float* __restrict__ Wk, const float* __restrict__ Wv,
    const float* __restrict__ Wp)
{
    int blk = blockIdx.x;
    const float* src;
    __half* dst;
    int local;
    if (blk < 2048)      { src = x;  dst = g_Xh;  local = blk; }
    else if (blk < 2560) { src = Wq; dst = g_Wqh; local = blk - 2048; }
    else if (blk < 3072) { src = Wk; dst = g_Wkh; local = blk - 2560; }
    else if (blk < 3584) { src = Wv; dst = g_Wvh; local = blk - 3072; }
    else                 { src = Wp; dst = g_Wph; local = blk - 3584; }
    int i = local * 256 + threadIdx.x;
    float4 v = *(const float4*)(src + 4 * (size_t)i);
    *(uint2*)((char*)dst + 8 * (size_t)i) = make_uint2(pack2h(v.x, v.y), pack2h(v.z, v.w));
}

// ---------------------------------------------------------------------------
// Kernel: QKV projection.  grid (8, 2, 192): z = qkv*64 + b*8 + h
// Q pre-scaled by 2^-4 (exact).  V is stored TRANSPOSED into g_Vth via a
// smem bounce (reuses the mainloop buffer) — no g_Vh, no vt kernel.
// ---------------------------------------------------------------------------
__global__ __launch_bounds__(256, 2) void qkv_g(
    const float* __restrict__ bq, const float* __restrict__ bk, const float* __restrict__ bv)
{
    extern __shared__ char sm[];
    int z = blockIdx.z, qkv = z >> 6, bh = z & 63, b = bh >> 3, h = bh & 7;
    int m0 = blockIdx.x * 128, n0 = blockIdx.y * 128;

    const __half* Wh = (qkv == 0) ? g_Wqh : (qkv == 1) ? g_Wkh : g_Wvh;
    const float* bias = ((qkv == 0) ? bq : (qkv == 1) ? bk : bv) + h * ND + n0;

    float acc[4][4][4];
    mma_gemm1(g_Xh + ((size_t)b * NS + m0) * ND,
              Wh + (size_t)h * ND * ND + (size_t)n0 * ND, ND, ND, 8, acc, sm);

    int lane = threadIdx.x & 31, wid = threadIdx.x >> 5;
    int wm = wid & 1, wn = wid >> 1;

    if (qkv < 2) {
        __half* Oh = (qkv == 0) ? g_Qh : g_Kh;
        float scale = (qkv == 0) ? 0.0625f : 1.0f;
        #pragma unroll
        for (int mf = 0; mf < 4; mf++) {
            int r = m0 + wm * 64 + mf * 16 + (lane >> 2);
            #pragma unroll
            for (int nf = 0; nf < 4; nf++) {
                int cc = wn * 32 + nf * 8 + ((lane & 3) << 1);
                float2 bb = *(const float2*)(bias + cc);
                size_t base0 = ((size_t)bh * NS + r) * ND + n0 + cc;
                size_t base1 = base0 + 8 * ND;
                *(uint32_t*)(Oh + base0) = pack2h((acc[mf][nf][0] + bb.x) * scale,
                                                  (acc[mf][nf][1] + bb.y) * scale);
                *(uint32_t*)(Oh + base1) = pack2h((acc[mf][nf][2] + bb.x) * scale,
                                                  (acc[mf][nf][3] + bb.y) * scale);
            }
        }
    } else {
        // V: bounce through smem [128][130] halves and store transposed.
        __syncthreads();                      // mainloop smem reads done
        __half* tsm = (__half*)sm;            // row stride 130 halves (260B, 4B-aligned)
        #pragma unroll
        for (int mf = 0; mf < 4; mf++) {
            int rl = wm * 64 + mf * 16 + (lane >> 2);
            #pragma unroll
            for (int nf = 0; nf < 4; nf++) {
                int cc = wn * 32 + nf * 8 + ((lane & 3) << 1);
                float2 bb = *(const float2*)(bias + cc);
                *(uint32_t*)(tsm + (size_t)rl * 130 + cc) =
                    pack2h(acc[mf][nf][0] + bb.x, acc[mf][nf][1] + bb.y);
                *(uint32_t*)(tsm + (size_t)(rl + 8) * 130 + cc) =
                    pack2h(acc[mf][nf][2] + bb.x, acc[mf][nf][3] + bb.y);
            }
        }
        __syncthreads();
        // warp wid handles e-rows [wid*16, wid*16+16); lane covers 4 s each.
        #pragma unroll
        for (int j = 0; j < 16; j++) {
            int er = wid * 16 + j;
            int s = lane * 4;
            uint32_t p0 = pack2h(__half2float(tsm[(size_t)(s + 0) * 130 + er]),
                                 __half2float(tsm[(size_t)(s + 1) * 130 + er]));
            uint32_t p1 = pack2h(__half2float(tsm[(size_t)(s + 2) * 130 + er]),
                                 __half2float(tsm[(size_t)(s + 3) * 130 + er]));
            *(uint2*)(g_Vth + ((size_t)bh * ND + n0 + er) * NS + m0 + s) = make_uint2(p0, p1);
        }
    }
}

// ---------------------------------------------------------------------------
// Kernel: scores = (Q/16) K^T -> fp16 logits.  grid (8, 8, 64)
// ---------------------------------------------------------------------------
__global__ __launch_bounds__(256, 2) void scores_g()
{
    extern __shared__ char sm[];
    int bh = blockIdx.z, m0 = blockIdx.x * 128, n0 = blockIdx.y * 128;
    float acc[4][4][4];
    mma_gemm1(g_Qh + ((size_t)bh * NS + m0) * ND,
              g_Kh + ((size_t)bh * NS + n0) * ND, ND, ND, 8, acc, sm);

    int lane = threadIdx.x & 31, wid = threadIdx.x >> 5;
    int wm = wid & 1, wn = wid >> 1;
    #pragma unroll
    for (int mf = 0; mf < 4; mf++) {
        int r = m0 + wm * 64 + mf * 16 + (lane >> 2);
        #pragma unroll
        for (int nf = 0; nf < 4; nf++) {
            int cc = n0 + wn * 32 + nf * 8 + ((lane & 3) << 1);
            __half* d0 = g_Ph + ((size_t)bh * NS + r) * NS + cc;
            *(uint32_t*)d0 = pack2h(acc[mf][nf][0], acc[mf][nf][1]);
            *(uint32_t*)(d0 + 8 * NS) = pack2h(acc[mf][nf][2], acc[mf][nf][3]);
        }
    }
}

// ---------------------------------------------------------------------------
// Kernel: warp-per-row in-place softmax on fp16 logits.  grid 8192, block 256
// Row = 1024 halves = 128 uint4; lane j reads uint4 at {lane, lane+32, +64, +96}.
// Pure shfl reductions — no smem, no barriers.
// ---------------------------------------------------------------------------
__global__ __launch_bounds__(256) void softmax_kernel()
{
    int wid = threadIdx.x >> 5, lane = threadIdx.x & 31;
    size_t row = (size_t)blockIdx.x * 8 + wid;
    uint4* pr = (uint4*)(g_Ph + row * NS);

    uint4 d[4];
    #pragma unroll
    for (int j = 0; j < 4; j++) d[j] = pr[lane + (j << 5)];

    float f[32];
    #pragma unroll
    for (int j = 0; j < 4; j++) {
        uint32_t w[4] = {d[j].x, d[j].y, d[j].z, d[j].w};
        #pragma unroll
        for (int k = 0; k < 4; k++) {
            float2 p = __half22float2(*(__half2*)&w[k]);
            f[j * 8 + k * 2]     = p.x;
            f[j * 8 + k * 2 + 1] = p.y;
        }
    }

    float m = f[0];
    #pragma unroll
    for (int i = 1; i < 32; i++) m = fmaxf(m, f[i]);
    #pragma unroll
    for (int o = 16; o > 0; o >>= 1) m = fmaxf(m, __shfl_xor_sync(0xffffffffu, m, o));

    float s = 0.f;
    #pragma unroll
    for (int i = 0; i < 32; i++) { f[i] = __expf(f[i] - m); s += f[i]; }
    #pragma unroll
    for (int o = 16; o > 0; o >>= 1) s += __shfl_xor_sync(0xffffffffu, s, o);
    float inv = 1.0f / s;

    #pragma unroll
    for (int j = 0; j < 4; j++) {
        uint4 o4;
        o4.x = pack2h(f[j*8+0] * inv, f[j*8+1] * inv);
        o4.y = pack2h(f[j*8+2] * inv, f[j*8+3] * inv);
        o4.z = pack2h(f[j*8+4] * inv, f[j*8+5] * inv);
        o4.w = pack2h(f[j*8+6] * inv, f[j*8+7] * inv);
        pr[lane + (j << 5)] = o4;
    }
}

// ---------------------------------------------------------------------------
// Kernel: O = P @ V (B = V^T).  grid (8, 2, 64) -> concat layout
// ---------------------------------------------------------------------------
__global__ __launch_bounds__(256, 2) void pv_g()
{
    extern __shared__ char sm[];
    int bh = blockIdx.z, b = bh >> 3, h = bh & 7;
    int m0 = blockIdx.x * 128, n0 = blockIdx.y * 128;
    float acc[4][4][4];
    mma_gemm1(g_Ph + ((size_t)bh * NS + m0) * NS,
              g_Vth + (size_t)bh * ND * NS + (size_t)n0 * NS, NS, NS, 32, acc, sm);

    int lane = threadIdx.x & 31, wid = threadIdx.x >> 5;
    int wm = wid & 1, wn = wid >> 1;
    #pragma unroll
    for (int mf = 0; mf < 4; mf++) {
        int r = m0 + wm * 64 + mf * 16 + (lane >> 2);
        #pragma unroll
        for (int nf = 0; nf < 4; nf++) {
            int cc = n0 + wn * 32 + nf * 8 + ((lane & 3) << 1);
            size_t base0 = ((size_t)(b * NS + r)) * HD + h * ND + cc;
            size_t base1 = base0 + 8 * HD;
            *(uint32_t*)(g_Oh + base0) = pack2h(acc[mf][nf][0], acc[mf][nf][1]);
            *(uint32_t*)(g_Oh + base1) = pack2h(acc[mf][nf][2], acc[mf][nf][3]);
        }
    }
}

// ---------------------------------------------------------------------------
// Kernel: out = concat(O) @ Wp^T.  grid (64, 2, 1)
// ---------------------------------------------------------------------------
__global__ __launch_bounds__(256, 2) void proj_g(float* __restrict__ out)
{
    extern __shared__ char sm[];
    int m0 = blockIdx.x * 128, n0 = blockIdx.y * 128;
    float acc[4][4][4];
    mma_gemm1(g_Oh + (size_t)m0 * HD, g_Wph + (size_t)n0 * HD,
              HD, HD, 64, acc, sm);

    int lane = threadIdx.x & 31, wid = threadIdx.x >> 5;
    int wm = wid & 1, wn = wid >> 1;
    #pragma unroll
    for (int mf = 0; mf < 4; mf++) {
        int r = m0 + wm * 64 + mf * 16 + (lane >> 2);
        #pragma unroll
        for (int nf = 0; nf < 4; nf++) {
            int cc = n0 + wn * 32 + nf * 8 + ((lane & 3) << 1);
            float* d0 = out + (size_t)r * ND + cc;
            *(float2*)d0 = make_float2(acc[mf][nf][0], acc[mf][nf][1]);
            *(float2*)(d0 + 8 * ND) = make_float2(acc[mf][nf][2], acc[mf][nf][3]);
        }
    }
}

// ---------------------------------------------------------------------------
extern "C" void kernel_launch(void* const* d_in, const int* in_sizes, int n_in,
                              void* d_out, int out_size)
{
    const float* x  = (const float*)d_in[0];
    const float* Wq = (const float*)d_in[1];
    const float* Wk = (const float*)d_in[2];
    const float* Wv = (const float*)d_in[3];
    const float* bq = (const float*)d_in[4];
    const float* bk = (const float*)d_in[5];
    const float* bv = (const float*)d_in[6];
    const float* Wp = (const float*)d_in[7];
    float* out = (float*)d_out;

    cudaFuncSetAttribute(qkv_g,    cudaFuncAttributeMaxDynamicSharedMemorySize, SMEM_G);
    cudaFuncSetAttribute(scores_g, cudaFuncAttributeMaxDynamicSharedMemorySize, SMEM_G);
    cudaFuncSetAttribute(pv_g,     cudaFuncAttributeMaxDynamicSharedMemorySize, SMEM_G);
    cudaFuncSetAttribute(proj_g,   cudaFuncAttributeMaxDynamicSharedMemorySize, SMEM_G);

    cvt_all<<<4096, 256>>>(x, Wq, Wk, Wv, Wp);

    dim3 gq(8, 2, 192);
    qkv_g<<<gq, 256, SMEM_G>>>(bq, bk, bv);

    dim3 gs(8, 8, 64);
    scores_g<<<gs, 256, SMEM_G>>>();

    softmax_kernel<<<8192, 256>>>();

    dim3 gp(8, 2, 64);
    pv_g<<<gp, 256, SMEM_G>>>();

    dim3 go(64, 2, 1);
    proj_g<<<go, 256, SMEM_G>>>(out);
}